// round 9
// baseline (speedup 1.0000x reference)
#include <cuda_runtime.h>
#include <cuda_bf16.h>
#include <math_constants.h>
#include <cstdint>

// Problem constants
#define BATCH 4
#define SEQ 2048
#define DIM 960
#define NH 15
#define NKV 5
#define HD 64
#define GQA 3
#define MTOK (BATCH*SEQ)   // 8192
#define QKV_N 1600         // 960 q + 320 k + 320 v

// ---------------- scratch (device globals; no allocations) ----------------
__device__ __nv_bfloat16 g_xhi[(size_t)MTOK * DIM];
__device__ __nv_bfloat16 g_xlo[(size_t)MTOK * DIM];
__device__ __nv_bfloat16 g_ahi[(size_t)MTOK * DIM];   // attention out hi
__device__ __nv_bfloat16 g_alo[(size_t)MTOK * DIM];   // attention out lo
__device__ __nv_bfloat16 g_qhi[(size_t)MTOK * NH * HD];
__device__ __nv_bfloat16 g_qlo[(size_t)MTOK * NH * HD];
__device__ __nv_bfloat16 g_khi[(size_t)MTOK * NKV * HD];
__device__ __nv_bfloat16 g_klo[(size_t)MTOK * NKV * HD];
__device__ __nv_bfloat16 g_vhi[(size_t)MTOK * NKV * HD];
__device__ __nv_bfloat16 g_vlo[(size_t)MTOK * NKV * HD];
__device__ __nv_bfloat16 g_wqkv_hi[(size_t)QKV_N * 960];
__device__ __nv_bfloat16 g_wqkv_lo[(size_t)QKV_N * 960];
__device__ __nv_bfloat16 g_wot_hi[(size_t)960 * 960];
__device__ __nv_bfloat16 g_wot_lo[(size_t)960 * 960];

// ---------------- small PTX helpers ------------------------------------------
__device__ __forceinline__ uint32_t smem_to_u32(const void* p) {
    uint32_t a;
    asm("{ .reg .u64 t; cvta.to.shared.u64 t, %1; cvt.u32.u64 %0, t; }" : "=r"(a) : "l"(p));
    return a;
}
__device__ __forceinline__ void cp_async16(uint32_t saddr, const void* gptr) {
    asm volatile("cp.async.cg.shared.global [%0], [%1], 16;" :: "r"(saddr), "l"(gptr));
}
#define CP_COMMIT() asm volatile("cp.async.commit_group;" ::: "memory")
#define CP_WAIT1()  asm volatile("cp.async.wait_group 1;" ::: "memory")

__device__ __forceinline__ void ldsm_x4(uint32_t* r, uint32_t addr) {
    asm volatile("ldmatrix.sync.aligned.m8n8.x4.shared.b16 {%0,%1,%2,%3}, [%4];"
                 : "=r"(r[0]), "=r"(r[1]), "=r"(r[2]), "=r"(r[3]) : "r"(addr));
}
__device__ __forceinline__ void ldsm_x4_trans(uint32_t* r, uint32_t addr) {
    asm volatile("ldmatrix.sync.aligned.m8n8.x4.trans.shared.b16 {%0,%1,%2,%3}, [%4];"
                 : "=r"(r[0]), "=r"(r[1]), "=r"(r[2]), "=r"(r[3]) : "r"(addr));
}
__device__ __forceinline__ void mma_bf16(float* d, const uint32_t* a, const uint32_t* b) {
    asm volatile(
        "mma.sync.aligned.m16n8k16.row.col.f32.bf16.bf16.f32 "
        "{%0,%1,%2,%3}, {%4,%5,%6,%7}, {%8,%9}, {%0,%1,%2,%3};"
        : "+f"(d[0]), "+f"(d[1]), "+f"(d[2]), "+f"(d[3])
        : "r"(a[0]), "r"(a[1]), "r"(a[2]), "r"(a[3]), "r"(b[0]), "r"(b[1]));
}
__device__ __forceinline__ uint32_t pack2bf(__nv_bfloat16 a, __nv_bfloat16 b) {
    __nv_bfloat162 t = __halves2bfloat162(a, b);
    return *(uint32_t*)&t;
}

// ---------------- bf16x3 GEMM core macros -------------------------------------
#define BM 128
#define BN 64
#define BK 32
#define NSTAGE 3
#define A_PITCH 80
#define SA_L (128 * A_PITCH)
#define SB_H (2 * 128 * A_PITCH)
#define STAGE_BYTES (SB_H + 2 * 64 * A_PITCH)    // 30720
#define GEMM_SMEM (NSTAGE * STAGE_BYTES)         // 92160

// Shared mainloop: computes acc[2][4][4] for C[M,N]=A@B^T tile (m0,n0).
#define GEMM_MAINLOOP(Ahi, Alo, Bhi, Blo, K)                                         \
    const uint32_t sbase = smem_to_u32(smem);                                        \
    const int tid  = threadIdx.x;                                                    \
    const int wid  = tid >> 5;                                                       \
    const int lane = tid & 31;                                                       \
    const int m0 = blockIdx.y * BM;                                                  \
    const int n0 = blockIdx.x * BN;                                                  \
    const int wm = wid >> 1;                                                         \
    const int wn = wid & 1;                                                          \
    const int nchunk = (K) / BK;                                                     \
    const int arow = tid >> 1;                                                       \
    const int acol = (tid & 1) * 2;                                                  \
    const int brow = tid >> 2;                                                       \
    const int bcol = tid & 3;                                                        \
    auto load_stage = [&](int ci, int s) {                                           \
        const uint32_t st = sbase + s * STAGE_BYTES;                                 \
        const int k0 = ci * BK;                                                      \
        {                                                                            \
            const size_t go = (size_t)(m0 + arow) * (K) + k0 + acol * 8;             \
            const uint32_t so = st + arow * A_PITCH + acol * 16;                     \
            cp_async16(so,             (Ahi) + go);                                  \
            cp_async16(so + 16,        (Ahi) + go + 8);                              \
            cp_async16(so + SA_L,      (Alo) + go);                                  \
            cp_async16(so + SA_L + 16, (Alo) + go + 8);                              \
        }                                                                            \
        {                                                                            \
            const size_t go = (size_t)(n0 + brow) * (K) + k0 + bcol * 8;             \
            const uint32_t so = st + SB_H + brow * A_PITCH + bcol * 16;              \
            cp_async16(so,                (Bhi) + go);                               \
            cp_async16(so + 64 * A_PITCH, (Blo) + go);                               \
        }                                                                            \
    };                                                                               \
    float acc[2][4][4];                                                              \
    _Pragma("unroll")                                                                \
    for (int i = 0; i < 2; i++)                                                      \
        _Pragma("unroll")                                                            \
        for (int j = 0; j < 4; j++)                                                  \
            _Pragma("unroll")                                                        \
            for (int v = 0; v < 4; v++) acc[i][j][v] = 0.f;                          \
    load_stage(0, 0); CP_COMMIT();                                                   \
    load_stage(1, 1); CP_COMMIT();                                                   \
    const int a_r   = lane & 15;                                                     \
    const int a_cb  = (lane >> 4) * 16;                                              \
    const int b_mat = lane >> 3;                                                     \
    const int b_rin = lane & 7;                                                      \
    const int b_nof = (b_mat >> 1) * 8 + b_rin;                                      \
    const int b_kb  = (b_mat & 1) * 16;                                              \
    for (int i = 0; i < nchunk; i++) {                                               \
        CP_WAIT1();                                                                  \
        __syncthreads();                                                             \
        if (i + 2 < nchunk) load_stage(i + 2, (i + 2) % NSTAGE);                     \
        CP_COMMIT();                                                                 \
        const uint32_t st = sbase + (i % NSTAGE) * STAGE_BYTES;                      \
        _Pragma("unroll")                                                            \
        for (int kk = 0; kk < 2; kk++) {                                             \
            const int kbyte = kk * 32;                                               \
            uint32_t ah[2][4], al[2][4], bh[8], bl[8];                               \
            _Pragma("unroll")                                                        \
            for (int mt = 0; mt < 2; mt++) {                                         \
                uint32_t addr = st + (wm * 32 + mt * 16 + a_r) * A_PITCH + kbyte + a_cb; \
                ldsm_x4(ah[mt], addr);                                               \
                ldsm_x4(al[mt], addr + SA_L);                                        \
            }                                                                        \
            _Pragma("unroll")                                                        \
            for (int hh = 0; hh < 2; hh++) {                                         \
                uint32_t addr = st + SB_H + (wn * 32 + hh * 16 + b_nof) * A_PITCH + kbyte + b_kb; \
                ldsm_x4(&bh[hh * 4], addr);                                          \
                ldsm_x4(&bl[hh * 4], addr + 64 * A_PITCH);                           \
            }                                                                        \
            _Pragma("unroll")                                                        \
            for (int mt = 0; mt < 2; mt++)                                           \
                _Pragma("unroll")                                                    \
                for (int nt = 0; nt < 4; nt++) {                                     \
                    mma_bf16(acc[mt][nt], ah[mt], &bh[nt * 2]);                      \
                    mma_bf16(acc[mt][nt], ah[mt], &bl[nt * 2]);                      \
                    mma_bf16(acc[mt][nt], al[mt], &bh[nt * 2]);                      \
                }                                                                    \
        }                                                                            \
        __syncthreads();                                                             \
    }

// ---------------- output-proj GEMM (fp32 epilogue) ----------------------------
__global__ void __launch_bounds__(256)
gemm_bf16x3_kernel(const __nv_bfloat16* __restrict__ Ahi,
                   const __nv_bfloat16* __restrict__ Alo,
                   const __nv_bfloat16* __restrict__ Bhi,
                   const __nv_bfloat16* __restrict__ Blo,
                   float* __restrict__ C, int M, int N, int K)
{
    extern __shared__ __align__(128) char smem[];
    GEMM_MAINLOOP(Ahi, Alo, Bhi, Blo, K)
#pragma unroll
    for (int mt = 0; mt < 2; mt++) {
#pragma unroll
        for (int nt = 0; nt < 4; nt++) {
            const int m = m0 + wm * 32 + mt * 16 + (lane >> 2);
            const int n = n0 + wn * 32 + nt * 8 + (lane & 3) * 2;
            *(float2*)&C[(size_t)m * N + n]       = make_float2(acc[mt][nt][0], acc[mt][nt][1]);
            *(float2*)&C[(size_t)(m + 8) * N + n] = make_float2(acc[mt][nt][2], acc[mt][nt][3]);
        }
    }
}

// ---------------- fused QKV GEMM with RoPE+split epilogue ---------------------
// N=1600: cols [0,960) -> q (rope, *0.125, hi+lo), [960,1280) -> k (rope, hi+lo),
// [1280,1600) -> v (hi+lo).
__global__ void __launch_bounds__(256)
gemm_qkv_kernel(const __nv_bfloat16* __restrict__ Ahi,
                const __nv_bfloat16* __restrict__ Alo,
                const __nv_bfloat16* __restrict__ Bhi,
                const __nv_bfloat16* __restrict__ Blo,
                const float* __restrict__ fcos, const float* __restrict__ fsin,
                __nv_bfloat16* __restrict__ qhi, __nv_bfloat16* __restrict__ qlo,
                __nv_bfloat16* __restrict__ khi, __nv_bfloat16* __restrict__ klo,
                __nv_bfloat16* __restrict__ vhi, __nv_bfloat16* __restrict__ vlo)
{
    extern __shared__ __align__(128) char smem[];
    GEMM_MAINLOOP(Ahi, Alo, Bhi, Blo, DIM)

    auto split_store = [&](__nv_bfloat16* hi, __nv_bfloat16* lo, size_t off,
                           float r0, float r1) {
        __nv_bfloat16 h0 = __float2bfloat16(r0), h1 = __float2bfloat16(r1);
        *(uint32_t*)(hi + off) = pack2bf(h0, h1);
        *(uint32_t*)(lo + off) = pack2bf(__float2bfloat16(r0 - __bfloat162float(h0)),
                                         __float2bfloat16(r1 - __bfloat162float(h1)));
    };

    auto store_pair = [&](int r, int n, float a0, float a1) {
        int t = r & (SEQ - 1);
        if (n < 960) {
            int i = (n & 63) >> 1;
            float c = fcos[t * 32 + i], s = fsin[t * 32 + i];
            split_store(qhi, qlo, (size_t)r * 960 + n,
                        (a0 * c - a1 * s) * 0.125f, (a0 * s + a1 * c) * 0.125f);
        } else if (n < 1280) {
            int i = (n & 63) >> 1;
            float c = fcos[t * 32 + i], s = fsin[t * 32 + i];
            split_store(khi, klo, (size_t)r * 320 + (n - 960),
                        a0 * c - a1 * s, a0 * s + a1 * c);
        } else {
            split_store(vhi, vlo, (size_t)r * 320 + (n - 1280), a0, a1);
        }
    };

#pragma unroll
    for (int mt = 0; mt < 2; mt++) {
#pragma unroll
        for (int nt = 0; nt < 4; nt++) {
            const int m = m0 + wm * 32 + mt * 16 + (lane >> 2);
            const int n = n0 + wn * 32 + nt * 8 + (lane & 3) * 2;
            store_pair(m,     n, acc[mt][nt][0], acc[mt][nt][1]);
            store_pair(m + 8, n, acc[mt][nt][2], acc[mt][nt][3]);
        }
    }
}

// ---------------- split / transpose helpers ---------------------------------
__global__ void convert_split_kernel(const float* __restrict__ src,
                                     __nv_bfloat16* __restrict__ hi,
                                     __nv_bfloat16* __restrict__ lo, int n) {
    int idx = blockIdx.x * blockDim.x + threadIdx.x;
    if (idx >= n) return;
    float a = src[idx];
    __nv_bfloat16 h = __float2bfloat16(a);
    hi[idx] = h;
    lo[idx] = __float2bfloat16(a - __bfloat162float(h));
}

__global__ void transpose_split_kernel(const float* __restrict__ W,
                                       __nv_bfloat16* __restrict__ hi,
                                       __nv_bfloat16* __restrict__ lo, int K, int N) {
    __shared__ float tile[32][33];
    int k0 = blockIdx.y * 32, n0 = blockIdx.x * 32;
    int tx = threadIdx.x, ty = threadIdx.y;
#pragma unroll
    for (int i = 0; i < 4; i++)
        tile[ty + i * 8][tx] = W[(size_t)(k0 + ty + i * 8) * N + n0 + tx];
    __syncthreads();
#pragma unroll
    for (int i = 0; i < 4; i++) {
        int n = n0 + ty + i * 8;
        float a = tile[tx][ty + i * 8];
        __nv_bfloat16 h = __float2bfloat16(a);
        hi[(size_t)n * K + k0 + tx] = h;
        lo[(size_t)n * K + k0 + tx] = __float2bfloat16(a - __bfloat162float(h));
    }
}

// ---------------- Flash attention on mma.sync (causal, GQA) -------------------
// Q hi+lo, K hi+lo, V hi+lo, P hi+lo. 3-pass QK, 3-pass PV.
// block: 128 threads (4 warps), 64 q rows; warp w owns rows w*16..w*16+15.
#define AT_PITCH 144
#define AT_K_L 9216
#define AT_V_H 18432
#define AT_V_L 27648
#define AT_STAGE 36864
#define ATTN_SMEM (2 * AT_STAGE)   // 73728

__global__ void __launch_bounds__(128)
attn_mma_kernel(const __nv_bfloat16* __restrict__ Qhi, const __nv_bfloat16* __restrict__ Qlo,
                const __nv_bfloat16* __restrict__ Khi, const __nv_bfloat16* __restrict__ Klo,
                const __nv_bfloat16* __restrict__ Vhi, const __nv_bfloat16* __restrict__ Vlo,
                __nv_bfloat16* __restrict__ Ohi, __nv_bfloat16* __restrict__ Olo)
{
    extern __shared__ __align__(128) char smem[];
    const uint32_t sbase = smem_to_u32(smem);
    const int tid = threadIdx.x, wid = tid >> 5, lane = tid & 31;
    const int qt = blockIdx.x, h = blockIdx.y, b = blockIdx.z;
    const int kvh = h / GQA;

    // ---- stage Q through smem (stage 0 area), extract fragments
    {
        int r = tid >> 1, half = tid & 1;
        size_t gq = ((size_t)(b * SEQ + qt * 64 + r) * NH + h) * HD + half * 32;
        const uint4* ph = (const uint4*)(Qhi + gq);
        const uint4* pl = (const uint4*)(Qlo + gq);
        char* dsth = smem + r * AT_PITCH + half * 64;
        char* dstl = smem + AT_K_L + r * AT_PITCH + half * 64;
#pragma unroll
        for (int c = 0; c < 4; c++) { ((uint4*)dsth)[c] = ph[c]; ((uint4*)dstl)[c] = pl[c]; }
    }
    __syncthreads();
    uint32_t qh[4][4], ql[4][4];
    {
        const int a_r = lane & 15, a_cb = (lane >> 4) * 16;
#pragma unroll
        for (int kk = 0; kk < 4; kk++) {
            uint32_t addr = sbase + (wid * 16 + a_r) * AT_PITCH + kk * 32 + a_cb;
            ldsm_x4(qh[kk], addr);
            ldsm_x4(ql[kk], addr + AT_K_L);
        }
    }
    __syncthreads();

    auto load_kv = [&](int kt) {
        uint32_t st = sbase + (kt & 1) * AT_STAGE;
        int jr = tid >> 1, cs = (tid & 1) * 4;
        size_t g = ((size_t)(b * SEQ + kt * 64 + jr) * NKV + kvh) * HD + cs * 8;
        uint32_t so = st + jr * AT_PITCH + cs * 16;
#pragma unroll
        for (int c = 0; c < 4; c++) {
            cp_async16(so + c * 16,           Khi + g + c * 8);
            cp_async16(so + AT_K_L + c * 16,  Klo + g + c * 8);
            cp_async16(so + AT_V_H + c * 16,  Vhi + g + c * 8);
            cp_async16(so + AT_V_L + c * 16,  Vlo + g + c * 8);
        }
    };

    float O[8][4];
#pragma unroll
    for (int i = 0; i < 8; i++)
#pragma unroll
        for (int j = 0; j < 4; j++) O[i][j] = 0.f;
    float m0 = -CUDART_INF_F, m1 = -CUDART_INF_F;
    float l0 = 0.f, l1 = 0.f;

    load_kv(0); CP_COMMIT();
    if (qt >= 1) load_kv(1);
    CP_COMMIT();

    const int b_rin = lane & 7;
    const int b_mat = lane >> 3;
    const int b_nof = (b_mat >> 1) * 8 + b_rin;
    const int b_kb  = (b_mat & 1) * 16;
    const int v_r   = lane & 15;
    const int v_cb  = (lane >> 4) * 16;
    const int r0loc = wid * 16 + (lane >> 2);

    for (int kt = 0; kt <= qt; kt++) {
        CP_WAIT1();
        __syncthreads();
        const uint32_t st = sbase + (kt & 1) * AT_STAGE;

        // ---- S = Q K^T (3-pass: Qh*Kh + Ql*Kh + Qh*Kl)
        float S[8][4];
#pragma unroll
        for (int i = 0; i < 8; i++)
#pragma unroll
            for (int j = 0; j < 4; j++) S[i][j] = 0.f;

#pragma unroll
        for (int kk = 0; kk < 4; kk++) {
            uint32_t kbh[16], kbl[16];
#pragma unroll
            for (int g2 = 0; g2 < 4; g2++) {
                uint32_t addr = st + (g2 * 16 + b_nof) * AT_PITCH + kk * 32 + b_kb;
                ldsm_x4(&kbh[g2 * 4], addr);
                ldsm_x4(&kbl[g2 * 4], addr + AT_K_L);
            }
#pragma unroll
            for (int nt = 0; nt < 8; nt++) {
                mma_bf16(S[nt], qh[kk], &kbh[nt * 2]);
                mma_bf16(S[nt], ql[kk], &kbh[nt * 2]);
                mma_bf16(S[nt], qh[kk], &kbl[nt * 2]);
            }
        }

        // ---- causal mask (diag tile only)
        if (kt == qt) {
#pragma unroll
            for (int nt = 0; nt < 8; nt++) {
                int col = nt * 8 + (lane & 3) * 2;
                if (col     > r0loc)     S[nt][0] = -CUDART_INF_F;
                if (col + 1 > r0loc)     S[nt][1] = -CUDART_INF_F;
                if (col     > r0loc + 8) S[nt][2] = -CUDART_INF_F;
                if (col + 1 > r0loc + 8) S[nt][3] = -CUDART_INF_F;
            }
        }

        // ---- online softmax
        float t0 = -CUDART_INF_F, t1 = -CUDART_INF_F;
#pragma unroll
        for (int nt = 0; nt < 8; nt++) {
            t0 = fmaxf(t0, fmaxf(S[nt][0], S[nt][1]));
            t1 = fmaxf(t1, fmaxf(S[nt][2], S[nt][3]));
        }
        t0 = fmaxf(t0, __shfl_xor_sync(0xffffffffu, t0, 1));
        t0 = fmaxf(t0, __shfl_xor_sync(0xffffffffu, t0, 2));
        t1 = fmaxf(t1, __shfl_xor_sync(0xffffffffu, t1, 1));
        t1 = fmaxf(t1, __shfl_xor_sync(0xffffffffu, t1, 2));
        float mn0 = fmaxf(m0, t0), mn1 = fmaxf(m1, t1);
        float c0 = __expf(m0 - mn0), c1 = __expf(m1 - mn1);
        m0 = mn0; m1 = mn1;

        // ---- P = exp(S - m), split hi/lo bf16
        uint32_t pkh[4][4], pkl[4][4];
        float la0 = 0.f, la1 = 0.f;
#pragma unroll
        for (int t = 0; t < 4; t++) {
            float p[8];
            p[0] = __expf(S[2*t][0] - mn0);   p[1] = __expf(S[2*t][1] - mn0);
            p[2] = __expf(S[2*t][2] - mn1);   p[3] = __expf(S[2*t][3] - mn1);
            p[4] = __expf(S[2*t+1][0] - mn0); p[5] = __expf(S[2*t+1][1] - mn0);
            p[6] = __expf(S[2*t+1][2] - mn1); p[7] = __expf(S[2*t+1][3] - mn1);
            la0 += p[0] + p[1] + p[4] + p[5];
            la1 += p[2] + p[3] + p[6] + p[7];
            __nv_bfloat16 hh[8], ll[8];
#pragma unroll
            for (int e = 0; e < 8; e++) {
                hh[e] = __float2bfloat16(p[e]);
                ll[e] = __float2bfloat16(p[e] - __bfloat162float(hh[e]));
            }
            pkh[t][0] = pack2bf(hh[0], hh[1]);  pkl[t][0] = pack2bf(ll[0], ll[1]);
            pkh[t][1] = pack2bf(hh[2], hh[3]);  pkl[t][1] = pack2bf(ll[2], ll[3]);
            pkh[t][2] = pack2bf(hh[4], hh[5]);  pkl[t][2] = pack2bf(ll[4], ll[5]);
            pkh[t][3] = pack2bf(hh[6], hh[7]);  pkl[t][3] = pack2bf(ll[6], ll[7]);
        }
        l0 = l0 * c0 + la0;
        l1 = l1 * c1 + la1;

#pragma unroll
        for (int dt = 0; dt < 8; dt++) {
            O[dt][0] *= c0; O[dt][1] *= c0;
            O[dt][2] *= c1; O[dt][3] *= c1;
        }

        // ---- O += P V (3-pass: Ph*Vh + Pl*Vh + Ph*Vl)
#pragma unroll
        for (int t = 0; t < 4; t++) {
            uint32_t vbh[16], vbl[16];
#pragma unroll
            for (int db = 0; db < 4; db++) {
                uint32_t addr = st + AT_V_H + (t * 16 + v_r) * AT_PITCH + db * 32 + v_cb;
                ldsm_x4_trans(&vbh[db * 4], addr);
                ldsm_x4_trans(&vbl[db * 4], addr + (AT_V_L - AT_V_H));
            }
#pragma unroll
            for (int dt = 0; dt < 8; dt++) {
                mma_bf16(O[dt], pkh[t], &vbh[dt * 2]);
                mma_bf16(O[dt], pkl[t], &vbh[dt * 2]);
                mma_bf16(O[dt], pkh[t], &vbl[dt * 2]);
            }
        }

        __syncthreads();
        if (kt + 2 <= qt) load_kv(kt + 2);
        CP_COMMIT();
    }

    // ---- finalize: normalize, split hi/lo, store
    l0 += __shfl_xor_sync(0xffffffffu, l0, 1);
    l0 += __shfl_xor_sync(0xffffffffu, l0, 2);
    l1 += __shfl_xor_sync(0xffffffffu, l1, 1);
    l1 += __shfl_xor_sync(0xffffffffu, l1, 2);
    float inv0 = 1.f / l0, inv1 = 1.f / l1;

    const int row0 = qt * 64 + r0loc;
#pragma unroll
    for (int dt = 0; dt < 8; dt++) {
        int d = dt * 8 + (lane & 3) * 2;
        size_t o0 = ((size_t)(b * SEQ + row0) * NH + h) * HD + d;
        size_t o1 = o0 + (size_t)8 * NH * HD;
        {
            float a = O[dt][0] * inv0, cc = O[dt][1] * inv0;
            __nv_bfloat16 ah = __float2bfloat16(a), ch = __float2bfloat16(cc);
            *(uint32_t*)(Ohi + o0) = pack2bf(ah, ch);
            *(uint32_t*)(Olo + o0) = pack2bf(__float2bfloat16(a - __bfloat162float(ah)),
                                             __float2bfloat16(cc - __bfloat162float(ch)));
        }
        {
            float a = O[dt][2] * inv1, cc = O[dt][3] * inv1;
            __nv_bfloat16 ah = __float2bfloat16(a), ch = __float2bfloat16(cc);
            *(uint32_t*)(Ohi + o1) = pack2bf(ah, ch);
            *(uint32_t*)(Olo + o1) = pack2bf(__float2bfloat16(a - __bfloat162float(ah)),
                                             __float2bfloat16(cc - __bfloat162float(ch)));
        }
    }
}

// ---------------- launcher ----------------------------------------------------
extern "C" void kernel_launch(void* const* d_in, const int* in_sizes, int n_in,
                              void* d_out, int out_size) {
    const float* x    = (const float*)d_in[0];
    const float* fcos = (const float*)d_in[1];
    const float* fsin = (const float*)d_in[2];
    const float* wq   = (const float*)d_in[3];
    const float* wk   = (const float*)d_in[4];
    const float* wv   = (const float*)d_in[5];
    const float* wo   = (const float*)d_in[6];
    float* out = (float*)d_out;

    __nv_bfloat16 *xhi, *xlo, *ahi, *alo, *qhi, *qlo, *khi, *klo, *vhi, *vlo;
    __nv_bfloat16 *wqkvh, *wqkvl, *woh, *wol;
    cudaGetSymbolAddress((void**)&xhi, g_xhi);
    cudaGetSymbolAddress((void**)&xlo, g_xlo);
    cudaGetSymbolAddress((void**)&ahi, g_ahi);
    cudaGetSymbolAddress((void**)&alo, g_alo);
    cudaGetSymbolAddress((void**)&qhi, g_qhi);
    cudaGetSymbolAddress((void**)&qlo, g_qlo);
    cudaGetSymbolAddress((void**)&khi, g_khi);
    cudaGetSymbolAddress((void**)&klo, g_klo);
    cudaGetSymbolAddress((void**)&vhi, g_vhi);
    cudaGetSymbolAddress((void**)&vlo, g_vlo);
    cudaGetSymbolAddress((void**)&wqkvh, g_wqkv_hi);
    cudaGetSymbolAddress((void**)&wqkvl, g_wqkv_lo);
    cudaGetSymbolAddress((void**)&woh, g_wot_hi);
    cudaGetSymbolAddress((void**)&wol, g_wot_lo);

    cudaFuncSetAttribute(gemm_bf16x3_kernel,
                         cudaFuncAttributeMaxDynamicSharedMemorySize, GEMM_SMEM);
    cudaFuncSetAttribute(gemm_qkv_kernel,
                         cudaFuncAttributeMaxDynamicSharedMemorySize, GEMM_SMEM);
    cudaFuncSetAttribute(attn_mma_kernel,
                         cudaFuncAttributeMaxDynamicSharedMemorySize, ATTN_SMEM);

    // input split + weight transposes/splits (wq/wk/wv concatenated rows)
    {
        int n = MTOK * DIM;
        convert_split_kernel<<<(n + 255) / 256, 256>>>(x, xhi, xlo, n);
    }
    transpose_split_kernel<<<dim3(960 / 32, 960 / 32), dim3(32, 8)>>>(
        wq, wqkvh, wqkvl, DIM, 960);
    transpose_split_kernel<<<dim3(320 / 32, 960 / 32), dim3(32, 8)>>>(
        wk, wqkvh + (size_t)960 * 960, wqkvl + (size_t)960 * 960, DIM, 320);
    transpose_split_kernel<<<dim3(320 / 32, 960 / 32), dim3(32, 8)>>>(
        wv, wqkvh + (size_t)1280 * 960, wqkvl + (size_t)1280 * 960, DIM, 320);
    transpose_split_kernel<<<dim3(960 / 32, 960 / 32), dim3(32, 8)>>>(wo, woh, wol, 960, 960);

    // fused QKV projection + RoPE + split epilogue
    gemm_qkv_kernel<<<dim3(QKV_N / BN, MTOK / BM), 256, GEMM_SMEM>>>(
        xhi, xlo, wqkvh, wqkvl, fcos, fsin, qhi, qlo, khi, klo, vhi, vlo);

    // flash attention on tensor cores -> bf16 hi/lo attention output
    attn_mma_kernel<<<dim3(SEQ / 64, NH, BATCH), 128, ATTN_SMEM>>>(
        qhi, qlo, khi, klo, vhi, vlo, ahi, alo);

    // output projection
    gemm_bf16x3_kernel<<<dim3(960 / BN, MTOK / BM), 256, GEMM_SMEM>>>(
        ahi, alo, woh, wol, out, MTOK, 960, 960);
}

// round 10
// speedup vs baseline: 1.5860x; 1.5860x over previous
#include <cuda_runtime.h>
#include <cuda_bf16.h>
#include <math_constants.h>
#include <cstdint>

// Problem constants
#define BATCH 4
#define SEQ 2048
#define DIM 960
#define NH 15
#define NKV 5
#define HD 64
#define GQA 3
#define MTOK (BATCH*SEQ)   // 8192
#define QKV_N 1600         // 960 q + 320 k + 320 v

// ---------------- scratch (device globals; no allocations) ----------------
__device__ __nv_bfloat16 g_xhi[(size_t)MTOK * DIM];
__device__ __nv_bfloat16 g_xlo[(size_t)MTOK * DIM];
__device__ __nv_bfloat16 g_ahi[(size_t)MTOK * DIM];   // attention out hi
__device__ __nv_bfloat16 g_alo[(size_t)MTOK * DIM];   // attention out lo
__device__ __nv_bfloat16 g_qhi[(size_t)MTOK * NH * HD];
__device__ __nv_bfloat16 g_qlo[(size_t)MTOK * NH * HD];
__device__ __nv_bfloat16 g_khi[(size_t)MTOK * NKV * HD];
__device__ __nv_bfloat16 g_klo[(size_t)MTOK * NKV * HD];
__device__ __nv_bfloat16 g_vhi[(size_t)MTOK * NKV * HD];
__device__ __nv_bfloat16 g_vlo[(size_t)MTOK * NKV * HD];
__device__ __nv_bfloat16 g_wqkv_hi[(size_t)QKV_N * 960];
__device__ __nv_bfloat16 g_wqkv_lo[(size_t)QKV_N * 960];
__device__ __nv_bfloat16 g_wot_hi[(size_t)960 * 960];
__device__ __nv_bfloat16 g_wot_lo[(size_t)960 * 960];

// ---------------- small PTX helpers ------------------------------------------
__device__ __forceinline__ uint32_t smem_to_u32(const void* p) {
    uint32_t a;
    asm("{ .reg .u64 t; cvta.to.shared.u64 t, %1; cvt.u32.u64 %0, t; }" : "=r"(a) : "l"(p));
    return a;
}
__device__ __forceinline__ void cp_async16(uint32_t saddr, const void* gptr) {
    asm volatile("cp.async.cg.shared.global [%0], [%1], 16;" :: "r"(saddr), "l"(gptr));
}
#define CP_COMMIT() asm volatile("cp.async.commit_group;" ::: "memory")
#define CP_WAIT1()  asm volatile("cp.async.wait_group 1;" ::: "memory")

__device__ __forceinline__ void ldsm_x4(uint32_t* r, uint32_t addr) {
    asm volatile("ldmatrix.sync.aligned.m8n8.x4.shared.b16 {%0,%1,%2,%3}, [%4];"
                 : "=r"(r[0]), "=r"(r[1]), "=r"(r[2]), "=r"(r[3]) : "r"(addr));
}
__device__ __forceinline__ void ldsm_x4_trans(uint32_t* r, uint32_t addr) {
    asm volatile("ldmatrix.sync.aligned.m8n8.x4.trans.shared.b16 {%0,%1,%2,%3}, [%4];"
                 : "=r"(r[0]), "=r"(r[1]), "=r"(r[2]), "=r"(r[3]) : "r"(addr));
}
__device__ __forceinline__ void mma_bf16(float* d, const uint32_t* a, const uint32_t* b) {
    asm volatile(
        "mma.sync.aligned.m16n8k16.row.col.f32.bf16.bf16.f32 "
        "{%0,%1,%2,%3}, {%4,%5,%6,%7}, {%8,%9}, {%0,%1,%2,%3};"
        : "+f"(d[0]), "+f"(d[1]), "+f"(d[2]), "+f"(d[3])
        : "r"(a[0]), "r"(a[1]), "r"(a[2]), "r"(a[3]), "r"(b[0]), "r"(b[1]));
}
__device__ __forceinline__ uint32_t pack2bf(__nv_bfloat16 a, __nv_bfloat16 b) {
    __nv_bfloat162 t = __halves2bfloat162(a, b);
    return *(uint32_t*)&t;
}

// ---------------- bf16x3 GEMM core macros -------------------------------------
#define BM 128
#define BN 64
#define BK 32
#define NSTAGE 3
#define A_PITCH 80
#define SA_L (128 * A_PITCH)
#define SB_H (2 * 128 * A_PITCH)
#define STAGE_BYTES (SB_H + 2 * 64 * A_PITCH)    // 30720
#define GEMM_SMEM (NSTAGE * STAGE_BYTES)         // 92160

// Shared mainloop: computes acc[2][4][4] for C[M,N]=A@B^T tile (m0,n0).
#define GEMM_MAINLOOP(Ahi, Alo, Bhi, Blo, K)                                         \
    const uint32_t sbase = smem_to_u32(smem);                                        \
    const int tid  = threadIdx.x;                                                    \
    const int wid  = tid >> 5;                                                       \
    const int lane = tid & 31;                                                       \
    const int m0 = blockIdx.y * BM;                                                  \
    const int n0 = blockIdx.x * BN;                                                  \
    const int wm = wid >> 1;                                                         \
    const int wn = wid & 1;                                                          \
    const int nchunk = (K) / BK;                                                     \
    const int arow = tid >> 1;                                                       \
    const int acol = (tid & 1) * 2;                                                  \
    const int brow = tid >> 2;                                                       \
    const int bcol = tid & 3;                                                        \
    auto load_stage = [&](int ci, int s) {                                           \
        const uint32_t st = sbase + s * STAGE_BYTES;                                 \
        const int k0 = ci * BK;                                                      \
        {                                                                            \
            const size_t go = (size_t)(m0 + arow) * (K) + k0 + acol * 8;             \
            const uint32_t so = st + arow * A_PITCH + acol * 16;                     \
            cp_async16(so,             (Ahi) + go);                                  \
            cp_async16(so + 16,        (Ahi) + go + 8);                              \
            cp_async16(so + SA_L,      (Alo) + go);                                  \
            cp_async16(so + SA_L + 16, (Alo) + go + 8);                              \
        }                                                                            \
        {                                                                            \
            const size_t go = (size_t)(n0 + brow) * (K) + k0 + bcol * 8;             \
            const uint32_t so = st + SB_H + brow * A_PITCH + bcol * 16;              \
            cp_async16(so,                (Bhi) + go);                               \
            cp_async16(so + 64 * A_PITCH, (Blo) + go);                               \
        }                                                                            \
    };                                                                               \
    float acc[2][4][4];                                                              \
    _Pragma("unroll")                                                                \
    for (int i = 0; i < 2; i++)                                                      \
        _Pragma("unroll")                                                            \
        for (int j = 0; j < 4; j++)                                                  \
            _Pragma("unroll")                                                        \
            for (int v = 0; v < 4; v++) acc[i][j][v] = 0.f;                          \
    load_stage(0, 0); CP_COMMIT();                                                   \
    load_stage(1, 1); CP_COMMIT();                                                   \
    const int a_r   = lane & 15;                                                     \
    const int a_cb  = (lane >> 4) * 16;                                              \
    const int b_mat = lane >> 3;                                                     \
    const int b_rin = lane & 7;                                                      \
    const int b_nof = (b_mat >> 1) * 8 + b_rin;                                      \
    const int b_kb  = (b_mat & 1) * 16;                                              \
    for (int i = 0; i < nchunk; i++) {                                               \
        CP_WAIT1();                                                                  \
        __syncthreads();                                                             \
        if (i + 2 < nchunk) load_stage(i + 2, (i + 2) % NSTAGE);                     \
        CP_COMMIT();                                                                 \
        const uint32_t st = sbase + (i % NSTAGE) * STAGE_BYTES;                      \
        _Pragma("unroll")                                                            \
        for (int kk = 0; kk < 2; kk++) {                                             \
            const int kbyte = kk * 32;                                               \
            uint32_t ah[2][4], al[2][4], bh[8], bl[8];                               \
            _Pragma("unroll")                                                        \
            for (int mt = 0; mt < 2; mt++) {                                         \
                uint32_t addr = st + (wm * 32 + mt * 16 + a_r) * A_PITCH + kbyte + a_cb; \
                ldsm_x4(ah[mt], addr);                                               \
                ldsm_x4(al[mt], addr + SA_L);                                        \
            }                                                                        \
            _Pragma("unroll")                                                        \
            for (int hh = 0; hh < 2; hh++) {                                         \
                uint32_t addr = st + SB_H + (wn * 32 + hh * 16 + b_nof) * A_PITCH + kbyte + b_kb; \
                ldsm_x4(&bh[hh * 4], addr);                                          \
                ldsm_x4(&bl[hh * 4], addr + 64 * A_PITCH);                           \
            }                                                                        \
            _Pragma("unroll")                                                        \
            for (int mt = 0; mt < 2; mt++)                                           \
                _Pragma("unroll")                                                    \
                for (int nt = 0; nt < 4; nt++) {                                     \
                    mma_bf16(acc[mt][nt], ah[mt], &bh[nt * 2]);                      \
                    mma_bf16(acc[mt][nt], ah[mt], &bl[nt * 2]);                      \
                    mma_bf16(acc[mt][nt], al[mt], &bh[nt * 2]);                      \
                }                                                                    \
        }                                                                            \
        __syncthreads();                                                             \
    }

// ---------------- output-proj GEMM (fp32 epilogue) ----------------------------
__global__ void __launch_bounds__(256, 2)
gemm_bf16x3_kernel(const __nv_bfloat16* __restrict__ Ahi,
                   const __nv_bfloat16* __restrict__ Alo,
                   const __nv_bfloat16* __restrict__ Bhi,
                   const __nv_bfloat16* __restrict__ Blo,
                   float* __restrict__ C, int M, int N, int K)
{
    extern __shared__ __align__(128) char smem[];
    GEMM_MAINLOOP(Ahi, Alo, Bhi, Blo, K)
#pragma unroll
    for (int mt = 0; mt < 2; mt++) {
#pragma unroll
        for (int nt = 0; nt < 4; nt++) {
            const int m = m0 + wm * 32 + mt * 16 + (lane >> 2);
            const int n = n0 + wn * 32 + nt * 8 + (lane & 3) * 2;
            *(float2*)&C[(size_t)m * N + n]       = make_float2(acc[mt][nt][0], acc[mt][nt][1]);
            *(float2*)&C[(size_t)(m + 8) * N + n] = make_float2(acc[mt][nt][2], acc[mt][nt][3]);
        }
    }
}

// ---------------- fused QKV GEMM with RoPE+split epilogue ---------------------
// N=1600: cols [0,960) -> q (rope, *0.125, hi+lo), [960,1280) -> k (rope, hi+lo),
// [1280,1600) -> v (hi+lo). Outputs via device symbols to cut register pressure;
// __launch_bounds__(256,2) forces <=128 regs so the mainloop keeps 2 CTAs/SM.
__global__ void __launch_bounds__(256, 2)
gemm_qkv_kernel(const __nv_bfloat16* __restrict__ Ahi,
                const __nv_bfloat16* __restrict__ Alo,
                const __nv_bfloat16* __restrict__ Bhi,
                const __nv_bfloat16* __restrict__ Blo,
                const float* __restrict__ fcos, const float* __restrict__ fsin)
{
    extern __shared__ __align__(128) char smem[];
    GEMM_MAINLOOP(Ahi, Alo, Bhi, Blo, DIM)

    auto split_store = [&](__nv_bfloat16* hi, __nv_bfloat16* lo, size_t off,
                           float r0, float r1) {
        __nv_bfloat16 h0 = __float2bfloat16(r0), h1 = __float2bfloat16(r1);
        *(uint32_t*)(hi + off) = pack2bf(h0, h1);
        *(uint32_t*)(lo + off) = pack2bf(__float2bfloat16(r0 - __bfloat162float(h0)),
                                         __float2bfloat16(r1 - __bfloat162float(h1)));
    };

    auto store_pair = [&](int r, int n, float a0, float a1) {
        int t = r & (SEQ - 1);
        if (n < 960) {
            int i = (n & 63) >> 1;
            float c = fcos[t * 32 + i], s = fsin[t * 32 + i];
            split_store(g_qhi, g_qlo, (size_t)r * 960 + n,
                        (a0 * c - a1 * s) * 0.125f, (a0 * s + a1 * c) * 0.125f);
        } else if (n < 1280) {
            int i = (n & 63) >> 1;
            float c = fcos[t * 32 + i], s = fsin[t * 32 + i];
            split_store(g_khi, g_klo, (size_t)r * 320 + (n - 960),
                        a0 * c - a1 * s, a0 * s + a1 * c);
        } else {
            split_store(g_vhi, g_vlo, (size_t)r * 320 + (n - 1280), a0, a1);
        }
    };

#pragma unroll
    for (int mt = 0; mt < 2; mt++) {
#pragma unroll
        for (int nt = 0; nt < 4; nt++) {
            const int m = m0 + wm * 32 + mt * 16 + (lane >> 2);
            const int n = n0 + wn * 32 + nt * 8 + (lane & 3) * 2;
            store_pair(m,     n, acc[mt][nt][0], acc[mt][nt][1]);
            store_pair(m + 8, n, acc[mt][nt][2], acc[mt][nt][3]);
        }
    }
}

// ---------------- split / transpose helpers ---------------------------------
__global__ void convert_split_kernel(const float* __restrict__ src,
                                     __nv_bfloat16* __restrict__ hi,
                                     __nv_bfloat16* __restrict__ lo, int n) {
    int idx = blockIdx.x * blockDim.x + threadIdx.x;
    if (idx >= n) return;
    float a = src[idx];
    __nv_bfloat16 h = __float2bfloat16(a);
    hi[idx] = h;
    lo[idx] = __float2bfloat16(a - __bfloat162float(h));
}

__global__ void transpose_split_kernel(const float* __restrict__ W,
                                       __nv_bfloat16* __restrict__ hi,
                                       __nv_bfloat16* __restrict__ lo, int K, int N) {
    __shared__ float tile[32][33];
    int k0 = blockIdx.y * 32, n0 = blockIdx.x * 32;
    int tx = threadIdx.x, ty = threadIdx.y;
#pragma unroll
    for (int i = 0; i < 4; i++)
        tile[ty + i * 8][tx] = W[(size_t)(k0 + ty + i * 8) * N + n0 + tx];
    __syncthreads();
#pragma unroll
    for (int i = 0; i < 4; i++) {
        int n = n0 + ty + i * 8;
        float a = tile[tx][ty + i * 8];
        __nv_bfloat16 h = __float2bfloat16(a);
        hi[(size_t)n * K + k0 + tx] = h;
        lo[(size_t)n * K + k0 + tx] = __float2bfloat16(a - __bfloat162float(h));
    }
}

// ---------------- Flash attention on mma.sync (causal, GQA) -------------------
// Q hi+lo, K hi+lo, V hi+lo, P hi+lo. 3-pass QK, 3-pass PV.
// block: 128 threads (4 warps), 64 q rows; warp w owns rows w*16..w*16+15.
#define AT_PITCH 144
#define AT_K_L 9216
#define AT_V_H 18432
#define AT_V_L 27648
#define AT_STAGE 36864
#define ATTN_SMEM (2 * AT_STAGE)   // 73728

__global__ void __launch_bounds__(128)
attn_mma_kernel(const __nv_bfloat16* __restrict__ Qhi, const __nv_bfloat16* __restrict__ Qlo,
                const __nv_bfloat16* __restrict__ Khi, const __nv_bfloat16* __restrict__ Klo,
                const __nv_bfloat16* __restrict__ Vhi, const __nv_bfloat16* __restrict__ Vlo,
                __nv_bfloat16* __restrict__ Ohi, __nv_bfloat16* __restrict__ Olo)
{
    extern __shared__ __align__(128) char smem[];
    const uint32_t sbase = smem_to_u32(smem);
    const int tid = threadIdx.x, wid = tid >> 5, lane = tid & 31;
    const int qt = blockIdx.x, h = blockIdx.y, b = blockIdx.z;
    const int kvh = h / GQA;

    // ---- stage Q through smem (stage 0 area), extract fragments
    {
        int r = tid >> 1, half = tid & 1;
        size_t gq = ((size_t)(b * SEQ + qt * 64 + r) * NH + h) * HD + half * 32;
        const uint4* ph = (const uint4*)(Qhi + gq);
        const uint4* pl = (const uint4*)(Qlo + gq);
        char* dsth = smem + r * AT_PITCH + half * 64;
        char* dstl = smem + AT_K_L + r * AT_PITCH + half * 64;
#pragma unroll
        for (int c = 0; c < 4; c++) { ((uint4*)dsth)[c] = ph[c]; ((uint4*)dstl)[c] = pl[c]; }
    }
    __syncthreads();
    uint32_t qh[4][4], ql[4][4];
    {
        const int a_r = lane & 15, a_cb = (lane >> 4) * 16;
#pragma unroll
        for (int kk = 0; kk < 4; kk++) {
            uint32_t addr = sbase + (wid * 16 + a_r) * AT_PITCH + kk * 32 + a_cb;
            ldsm_x4(qh[kk], addr);
            ldsm_x4(ql[kk], addr + AT_K_L);
        }
    }
    __syncthreads();

    auto load_kv = [&](int kt) {
        uint32_t st = sbase + (kt & 1) * AT_STAGE;
        int jr = tid >> 1, cs = (tid & 1) * 4;
        size_t g = ((size_t)(b * SEQ + kt * 64 + jr) * NKV + kvh) * HD + cs * 8;
        uint32_t so = st + jr * AT_PITCH + cs * 16;
#pragma unroll
        for (int c = 0; c < 4; c++) {
            cp_async16(so + c * 16,           Khi + g + c * 8);
            cp_async16(so + AT_K_L + c * 16,  Klo + g + c * 8);
            cp_async16(so + AT_V_H + c * 16,  Vhi + g + c * 8);
            cp_async16(so + AT_V_L + c * 16,  Vlo + g + c * 8);
        }
    };

    float O[8][4];
#pragma unroll
    for (int i = 0; i < 8; i++)
#pragma unroll
        for (int j = 0; j < 4; j++) O[i][j] = 0.f;
    float m0 = -CUDART_INF_F, m1 = -CUDART_INF_F;
    float l0 = 0.f, l1 = 0.f;

    load_kv(0); CP_COMMIT();
    if (qt >= 1) load_kv(1);
    CP_COMMIT();

    const int b_rin = lane & 7;
    const int b_mat = lane >> 3;
    const int b_nof = (b_mat >> 1) * 8 + b_rin;
    const int b_kb  = (b_mat & 1) * 16;
    const int v_r   = lane & 15;
    const int v_cb  = (lane >> 4) * 16;
    const int r0loc = wid * 16 + (lane >> 2);

    for (int kt = 0; kt <= qt; kt++) {
        CP_WAIT1();
        __syncthreads();
        const uint32_t st = sbase + (kt & 1) * AT_STAGE;

        // ---- S = Q K^T (3-pass: Qh*Kh + Ql*Kh + Qh*Kl)
        float S[8][4];
#pragma unroll
        for (int i = 0; i < 8; i++)
#pragma unroll
            for (int j = 0; j < 4; j++) S[i][j] = 0.f;

#pragma unroll
        for (int kk = 0; kk < 4; kk++) {
            uint32_t kbh[16], kbl[16];
#pragma unroll
            for (int g2 = 0; g2 < 4; g2++) {
                uint32_t addr = st + (g2 * 16 + b_nof) * AT_PITCH + kk * 32 + b_kb;
                ldsm_x4(&kbh[g2 * 4], addr);
                ldsm_x4(&kbl[g2 * 4], addr + AT_K_L);
            }
#pragma unroll
            for (int nt = 0; nt < 8; nt++) {
                mma_bf16(S[nt], qh[kk], &kbh[nt * 2]);
                mma_bf16(S[nt], ql[kk], &kbh[nt * 2]);
                mma_bf16(S[nt], qh[kk], &kbl[nt * 2]);
            }
        }

        // ---- causal mask (diag tile only)
        if (kt == qt) {
#pragma unroll
            for (int nt = 0; nt < 8; nt++) {
                int col = nt * 8 + (lane & 3) * 2;
                if (col     > r0loc)     S[nt][0] = -CUDART_INF_F;
                if (col + 1 > r0loc)     S[nt][1] = -CUDART_INF_F;
                if (col     > r0loc + 8) S[nt][2] = -CUDART_INF_F;
                if (col + 1 > r0loc + 8) S[nt][3] = -CUDART_INF_F;
            }
        }

        // ---- online softmax
        float t0 = -CUDART_INF_F, t1 = -CUDART_INF_F;
#pragma unroll
        for (int nt = 0; nt < 8; nt++) {
            t0 = fmaxf(t0, fmaxf(S[nt][0], S[nt][1]));
            t1 = fmaxf(t1, fmaxf(S[nt][2], S[nt][3]));
        }
        t0 = fmaxf(t0, __shfl_xor_sync(0xffffffffu, t0, 1));
        t0 = fmaxf(t0, __shfl_xor_sync(0xffffffffu, t0, 2));
        t1 = fmaxf(t1, __shfl_xor_sync(0xffffffffu, t1, 1));
        t1 = fmaxf(t1, __shfl_xor_sync(0xffffffffu, t1, 2));
        float mn0 = fmaxf(m0, t0), mn1 = fmaxf(m1, t1);
        float c0 = __expf(m0 - mn0), c1 = __expf(m1 - mn1);
        m0 = mn0; m1 = mn1;

        // ---- P = exp(S - m), split hi/lo bf16
        uint32_t pkh[4][4], pkl[4][4];
        float la0 = 0.f, la1 = 0.f;
#pragma unroll
        for (int t = 0; t < 4; t++) {
            float p[8];
            p[0] = __expf(S[2*t][0] - mn0);   p[1] = __expf(S[2*t][1] - mn0);
            p[2] = __expf(S[2*t][2] - mn1);   p[3] = __expf(S[2*t][3] - mn1);
            p[4] = __expf(S[2*t+1][0] - mn0); p[5] = __expf(S[2*t+1][1] - mn0);
            p[6] = __expf(S[2*t+1][2] - mn1); p[7] = __expf(S[2*t+1][3] - mn1);
            la0 += p[0] + p[1] + p[4] + p[5];
            la1 += p[2] + p[3] + p[6] + p[7];
            __nv_bfloat16 hh[8], ll[8];
#pragma unroll
            for (int e = 0; e < 8; e++) {
                hh[e] = __float2bfloat16(p[e]);
                ll[e] = __float2bfloat16(p[e] - __bfloat162float(hh[e]));
            }
            pkh[t][0] = pack2bf(hh[0], hh[1]);  pkl[t][0] = pack2bf(ll[0], ll[1]);
            pkh[t][1] = pack2bf(hh[2], hh[3]);  pkl[t][1] = pack2bf(ll[2], ll[3]);
            pkh[t][2] = pack2bf(hh[4], hh[5]);  pkl[t][2] = pack2bf(ll[4], ll[5]);
            pkh[t][3] = pack2bf(hh[6], hh[7]);  pkl[t][3] = pack2bf(ll[6], ll[7]);
        }
        l0 = l0 * c0 + la0;
        l1 = l1 * c1 + la1;

#pragma unroll
        for (int dt = 0; dt < 8; dt++) {
            O[dt][0] *= c0; O[dt][1] *= c0;
            O[dt][2] *= c1; O[dt][3] *= c1;
        }

        // ---- O += P V (3-pass: Ph*Vh + Pl*Vh + Ph*Vl)
#pragma unroll
        for (int t = 0; t < 4; t++) {
            uint32_t vbh[16], vbl[16];
#pragma unroll
            for (int db = 0; db < 4; db++) {
                uint32_t addr = st + AT_V_H + (t * 16 + v_r) * AT_PITCH + db * 32 + v_cb;
                ldsm_x4_trans(&vbh[db * 4], addr);
                ldsm_x4_trans(&vbl[db * 4], addr + (AT_V_L - AT_V_H));
            }
#pragma unroll
            for (int dt = 0; dt < 8; dt++) {
                mma_bf16(O[dt], pkh[t], &vbh[dt * 2]);
                mma_bf16(O[dt], pkl[t], &vbh[dt * 2]);
                mma_bf16(O[dt], pkh[t], &vbl[dt * 2]);
            }
        }

        __syncthreads();
        if (kt + 2 <= qt) load_kv(kt + 2);
        CP_COMMIT();
    }

    // ---- finalize: normalize, split hi/lo, store
    l0 += __shfl_xor_sync(0xffffffffu, l0, 1);
    l0 += __shfl_xor_sync(0xffffffffu, l0, 2);
    l1 += __shfl_xor_sync(0xffffffffu, l1, 1);
    l1 += __shfl_xor_sync(0xffffffffu, l1, 2);
    float inv0 = 1.f / l0, inv1 = 1.f / l1;

    const int row0 = qt * 64 + r0loc;
#pragma unroll
    for (int dt = 0; dt < 8; dt++) {
        int d = dt * 8 + (lane & 3) * 2;
        size_t o0 = ((size_t)(b * SEQ + row0) * NH + h) * HD + d;
        size_t o1 = o0 + (size_t)8 * NH * HD;
        {
            float a = O[dt][0] * inv0, cc = O[dt][1] * inv0;
            __nv_bfloat16 ah = __float2bfloat16(a), ch = __float2bfloat16(cc);
            *(uint32_t*)(Ohi + o0) = pack2bf(ah, ch);
            *(uint32_t*)(Olo + o0) = pack2bf(__float2bfloat16(a - __bfloat162float(ah)),
                                             __float2bfloat16(cc - __bfloat162float(ch)));
        }
        {
            float a = O[dt][2] * inv1, cc = O[dt][3] * inv1;
            __nv_bfloat16 ah = __float2bfloat16(a), ch = __float2bfloat16(cc);
            *(uint32_t*)(Ohi + o1) = pack2bf(ah, ch);
            *(uint32_t*)(Olo + o1) = pack2bf(__float2bfloat16(a - __bfloat162float(ah)),
                                             __float2bfloat16(cc - __bfloat162float(ch)));
        }
    }
}

// ---------------- launcher ----------------------------------------------------
extern "C" void kernel_launch(void* const* d_in, const int* in_sizes, int n_in,
                              void* d_out, int out_size) {
    const float* x    = (const float*)d_in[0];
    const float* fcos = (const float*)d_in[1];
    const float* fsin = (const float*)d_in[2];
    const float* wq   = (const float*)d_in[3];
    const float* wk   = (const float*)d_in[4];
    const float* wv   = (const float*)d_in[5];
    const float* wo   = (const float*)d_in[6];
    float* out = (float*)d_out;

    __nv_bfloat16 *xhi, *xlo, *ahi, *alo, *qhi, *qlo, *khi, *klo, *vhi, *vlo;
    __nv_bfloat16 *wqkvh, *wqkvl, *woh, *wol;
    cudaGetSymbolAddress((void**)&xhi, g_xhi);
    cudaGetSymbolAddress((void**)&xlo, g_xlo);
    cudaGetSymbolAddress((void**)&ahi, g_ahi);
    cudaGetSymbolAddress((void**)&alo, g_alo);
    cudaGetSymbolAddress((void**)&qhi, g_qhi);
    cudaGetSymbolAddress((void**)&qlo, g_qlo);
    cudaGetSymbolAddress((void**)&khi, g_khi);
    cudaGetSymbolAddress((void**)&klo, g_klo);
    cudaGetSymbolAddress((void**)&vhi, g_vhi);
    cudaGetSymbolAddress((void**)&vlo, g_vlo);
    cudaGetSymbolAddress((void**)&wqkvh, g_wqkv_hi);
    cudaGetSymbolAddress((void**)&wqkvl, g_wqkv_lo);
    cudaGetSymbolAddress((void**)&woh, g_wot_hi);
    cudaGetSymbolAddress((void**)&wol, g_wot_lo);

    cudaFuncSetAttribute(gemm_bf16x3_kernel,
                         cudaFuncAttributeMaxDynamicSharedMemorySize, GEMM_SMEM);
    cudaFuncSetAttribute(gemm_qkv_kernel,
                         cudaFuncAttributeMaxDynamicSharedMemorySize, GEMM_SMEM);
    cudaFuncSetAttribute(attn_mma_kernel,
                         cudaFuncAttributeMaxDynamicSharedMemorySize, ATTN_SMEM);

    // input split + weight transposes/splits (wq/wk/wv concatenated rows)
    {
        int n = MTOK * DIM;
        convert_split_kernel<<<(n + 255) / 256, 256>>>(x, xhi, xlo, n);
    }
    transpose_split_kernel<<<dim3(960 / 32, 960 / 32), dim3(32, 8)>>>(
        wq, wqkvh, wqkvl, DIM, 960);
    transpose_split_kernel<<<dim3(320 / 32, 960 / 32), dim3(32, 8)>>>(
        wk, wqkvh + (size_t)960 * 960, wqkvl + (size_t)960 * 960, DIM, 320);
    transpose_split_kernel<<<dim3(320 / 32, 960 / 32), dim3(32, 8)>>>(
        wv, wqkvh + (size_t)1280 * 960, wqkvl + (size_t)1280 * 960, DIM, 320);
    transpose_split_kernel<<<dim3(960 / 32, 960 / 32), dim3(32, 8)>>>(wo, woh, wol, 960, 960);

    // fused QKV projection + RoPE + split epilogue
    gemm_qkv_kernel<<<dim3(QKV_N / BN, MTOK / BM), 256, GEMM_SMEM>>>(
        xhi, xlo, wqkvh, wqkvl, fcos, fsin);

    // flash attention on tensor cores -> bf16 hi/lo attention output
    attn_mma_kernel<<<dim3(SEQ / 64, NH, BATCH), 128, ATTN_SMEM>>>(
        qhi, qlo, khi, klo, vhi, vlo, ahi, alo);

    // output projection
    gemm_bf16x3_kernel<<<dim3(960 / BN, MTOK / BM), 256, GEMM_SMEM>>>(
        ahi, alo, woh, wol, out, MTOK, 960, 960);
}

// round 11
// speedup vs baseline: 1.9567x; 1.2337x over previous
#include <cuda_runtime.h>
#include <cuda_bf16.h>
#include <cuda_fp16.h>
#include <math_constants.h>
#include <cstdint>

// Problem constants
#define BATCH 4
#define SEQ 2048
#define DIM 960
#define NH 15
#define NKV 5
#define HD 64
#define GQA 3
#define MTOK (BATCH*SEQ)   // 8192
#define QKV_N 1600         // 960 q + 320 k + 320 v

// ---------------- scratch (device globals; no allocations) ----------------
__device__ __nv_bfloat16 g_xhi[(size_t)MTOK * DIM];
__device__ __nv_bfloat16 g_xlo[(size_t)MTOK * DIM];
__device__ __nv_bfloat16 g_ahi[(size_t)MTOK * DIM];   // attention out hi
__device__ __nv_bfloat16 g_alo[(size_t)MTOK * DIM];   // attention out lo
__device__ __half g_q16h[(size_t)MTOK * NH * HD];
__device__ __half g_q16l[(size_t)MTOK * NH * HD];
__device__ __half g_k16[(size_t)MTOK * NKV * HD];
__device__ __half g_v16[(size_t)MTOK * NKV * HD];
__device__ __nv_bfloat16 g_wqkv_hi[(size_t)QKV_N * 960];
__device__ __nv_bfloat16 g_wqkv_lo[(size_t)QKV_N * 960];
__device__ __nv_bfloat16 g_wot_hi[(size_t)960 * 960];
__device__ __nv_bfloat16 g_wot_lo[(size_t)960 * 960];

// ---------------- small PTX helpers ------------------------------------------
__device__ __forceinline__ uint32_t smem_to_u32(const void* p) {
    uint32_t a;
    asm("{ .reg .u64 t; cvta.to.shared.u64 t, %1; cvt.u32.u64 %0, t; }" : "=r"(a) : "l"(p));
    return a;
}
__device__ __forceinline__ void cp_async16(uint32_t saddr, const void* gptr) {
    asm volatile("cp.async.cg.shared.global [%0], [%1], 16;" :: "r"(saddr), "l"(gptr));
}
#define CP_COMMIT() asm volatile("cp.async.commit_group;" ::: "memory")
#define CP_WAIT1()  asm volatile("cp.async.wait_group 1;" ::: "memory")

__device__ __forceinline__ void ldsm_x4(uint32_t* r, uint32_t addr) {
    asm volatile("ldmatrix.sync.aligned.m8n8.x4.shared.b16 {%0,%1,%2,%3}, [%4];"
                 : "=r"(r[0]), "=r"(r[1]), "=r"(r[2]), "=r"(r[3]) : "r"(addr));
}
__device__ __forceinline__ void ldsm_x4_trans(uint32_t* r, uint32_t addr) {
    asm volatile("ldmatrix.sync.aligned.m8n8.x4.trans.shared.b16 {%0,%1,%2,%3}, [%4];"
                 : "=r"(r[0]), "=r"(r[1]), "=r"(r[2]), "=r"(r[3]) : "r"(addr));
}
__device__ __forceinline__ void mma_bf16(float* d, const uint32_t* a, const uint32_t* b) {
    asm volatile(
        "mma.sync.aligned.m16n8k16.row.col.f32.bf16.bf16.f32 "
        "{%0,%1,%2,%3}, {%4,%5,%6,%7}, {%8,%9}, {%0,%1,%2,%3};"
        : "+f"(d[0]), "+f"(d[1]), "+f"(d[2]), "+f"(d[3])
        : "r"(a[0]), "r"(a[1]), "r"(a[2]), "r"(a[3]), "r"(b[0]), "r"(b[1]));
}
__device__ __forceinline__ void mma_f16(float* d, const uint32_t* a, const uint32_t* b) {
    asm volatile(
        "mma.sync.aligned.m16n8k16.row.col.f32.f16.f16.f32 "
        "{%0,%1,%2,%3}, {%4,%5,%6,%7}, {%8,%9}, {%0,%1,%2,%3};"
        : "+f"(d[0]), "+f"(d[1]), "+f"(d[2]), "+f"(d[3])
        : "r"(a[0]), "r"(a[1]), "r"(a[2]), "r"(a[3]), "r"(b[0]), "r"(b[1]));
}
__device__ __forceinline__ uint32_t pack2bf(__nv_bfloat16 a, __nv_bfloat16 b) {
    __nv_bfloat162 t = __halves2bfloat162(a, b);
    return *(uint32_t*)&t;
}
__device__ __forceinline__ uint32_t pack2h(__half a, __half b) {
    __half2 t = __halves2half2(a, b);
    return *(uint32_t*)&t;
}

// ---------------- bf16x3 GEMM core macros -------------------------------------
#define BM 128
#define BN 64
#define BK 32
#define NSTAGE 3
#define A_PITCH 80
#define SA_L (128 * A_PITCH)
#define SB_H (2 * 128 * A_PITCH)
#define STAGE_BYTES (SB_H + 2 * 64 * A_PITCH)    // 30720
#define GEMM_SMEM (NSTAGE * STAGE_BYTES)         // 92160

// Shared mainloop: computes acc[2][4][4] for C[M,N]=A@B^T tile (m0,n0).
#define GEMM_MAINLOOP(Ahi, Alo, Bhi, Blo, K)                                         \
    const uint32_t sbase = smem_to_u32(smem);                                        \
    const int tid  = threadIdx.x;                                                    \
    const int wid  = tid >> 5;                                                       \
    const int lane = tid & 31;                                                       \
    const int m0 = blockIdx.y * BM;                                                  \
    const int n0 = blockIdx.x * BN;                                                  \
    const int wm = wid >> 1;                                                         \
    const int wn = wid & 1;                                                          \
    const int nchunk = (K) / BK;                                                     \
    const int arow = tid >> 1;                                                       \
    const int acol = (tid & 1) * 2;                                                  \
    const int brow = tid >> 2;                                                       \
    const int bcol = tid & 3;                                                        \
    auto load_stage = [&](int ci, int s) {                                           \
        const uint32_t st = sbase + s * STAGE_BYTES;                                 \
        const int k0 = ci * BK;                                                      \
        {                                                                            \
            const size_t go = (size_t)(m0 + arow) * (K) + k0 + acol * 8;             \
            const uint32_t so = st + arow * A_PITCH + acol * 16;                     \
            cp_async16(so,             (Ahi) + go);                                  \
            cp_async16(so + 16,        (Ahi) + go + 8);                              \
            cp_async16(so + SA_L,      (Alo) + go);                                  \
            cp_async16(so + SA_L + 16, (Alo) + go + 8);                              \
        }                                                                            \
        {                                                                            \
            const size_t go = (size_t)(n0 + brow) * (K) + k0 + bcol * 8;             \
            const uint32_t so = st + SB_H + brow * A_PITCH + bcol * 16;              \
            cp_async16(so,                (Bhi) + go);                               \
            cp_async16(so + 64 * A_PITCH, (Blo) + go);                               \
        }                                                                            \
    };                                                                               \
    float acc[2][4][4];                                                              \
    _Pragma("unroll")                                                                \
    for (int i = 0; i < 2; i++)                                                      \
        _Pragma("unroll")                                                            \
        for (int j = 0; j < 4; j++)                                                  \
            _Pragma("unroll")                                                        \
            for (int v = 0; v < 4; v++) acc[i][j][v] = 0.f;                          \
    load_stage(0, 0); CP_COMMIT();                                                   \
    load_stage(1, 1); CP_COMMIT();                                                   \
    const int a_r   = lane & 15;                                                     \
    const int a_cb  = (lane >> 4) * 16;                                              \
    const int b_mat = lane >> 3;                                                     \
    const int b_rin = lane & 7;                                                      \
    const int b_nof = (b_mat >> 1) * 8 + b_rin;                                      \
    const int b_kb  = (b_mat & 1) * 16;                                              \
    for (int i = 0; i < nchunk; i++) {                                               \
        CP_WAIT1();                                                                  \
        __syncthreads();                                                             \
        if (i + 2 < nchunk) load_stage(i + 2, (i + 2) % NSTAGE);                     \
        CP_COMMIT();                                                                 \
        const uint32_t st = sbase + (i % NSTAGE) * STAGE_BYTES;                      \
        _Pragma("unroll")                                                            \
        for (int kk = 0; kk < 2; kk++) {                                             \
            const int kbyte = kk * 32;                                               \
            uint32_t ah[2][4], al[2][4], bh[8], bl[8];                               \
            _Pragma("unroll")                                                        \
            for (int mt = 0; mt < 2; mt++) {                                         \
                uint32_t addr = st + (wm * 32 + mt * 16 + a_r) * A_PITCH + kbyte + a_cb; \
                ldsm_x4(ah[mt], addr);                                               \
                ldsm_x4(al[mt], addr + SA_L);                                        \
            }                                                                        \
            _Pragma("unroll")                                                        \
            for (int hh = 0; hh < 2; hh++) {                                         \
                uint32_t addr = st + SB_H + (wn * 32 + hh * 16 + b_nof) * A_PITCH + kbyte + b_kb; \
                ldsm_x4(&bh[hh * 4], addr);                                          \
                ldsm_x4(&bl[hh * 4], addr + 64 * A_PITCH);                           \
            }                                                                        \
            _Pragma("unroll")                                                        \
            for (int mt = 0; mt < 2; mt++)                                           \
                _Pragma("unroll")                                                    \
                for (int nt = 0; nt < 4; nt++) {                                     \
                    mma_bf16(acc[mt][nt], ah[mt], &bh[nt * 2]);                      \
                    mma_bf16(acc[mt][nt], ah[mt], &bl[nt * 2]);                      \
                    mma_bf16(acc[mt][nt], al[mt], &bh[nt * 2]);                      \
                }                                                                    \
        }                                                                            \
        __syncthreads();                                                             \
    }

// ---------------- output-proj GEMM (fp32 epilogue) ----------------------------
__global__ void __launch_bounds__(256, 2)
gemm_bf16x3_kernel(const __nv_bfloat16* __restrict__ Ahi,
                   const __nv_bfloat16* __restrict__ Alo,
                   const __nv_bfloat16* __restrict__ Bhi,
                   const __nv_bfloat16* __restrict__ Blo,
                   float* __restrict__ C, int M, int N, int K)
{
    extern __shared__ __align__(128) char smem[];
    GEMM_MAINLOOP(Ahi, Alo, Bhi, Blo, K)
#pragma unroll
    for (int mt = 0; mt < 2; mt++) {
#pragma unroll
        for (int nt = 0; nt < 4; nt++) {
            const int m = m0 + wm * 32 + mt * 16 + (lane >> 2);
            const int n = n0 + wn * 32 + nt * 8 + (lane & 3) * 2;
            *(float2*)&C[(size_t)m * N + n]       = make_float2(acc[mt][nt][0], acc[mt][nt][1]);
            *(float2*)&C[(size_t)(m + 8) * N + n] = make_float2(acc[mt][nt][2], acc[mt][nt][3]);
        }
    }
}

// ---------------- fused QKV GEMM with RoPE+split epilogue ---------------------
// N=1600: cols [0,960) -> q (rope, *0.125, fp16 hi+lo), [960,1280) -> k (rope, fp16),
// [1280,1600) -> v (fp16). Outputs via device symbols to cut register pressure.
__global__ void __launch_bounds__(256, 2)
gemm_qkv_kernel(const __nv_bfloat16* __restrict__ Ahi,
                const __nv_bfloat16* __restrict__ Alo,
                const __nv_bfloat16* __restrict__ Bhi,
                const __nv_bfloat16* __restrict__ Blo,
                const float* __restrict__ fcos, const float* __restrict__ fsin)
{
    extern __shared__ __align__(128) char smem[];
    GEMM_MAINLOOP(Ahi, Alo, Bhi, Blo, DIM)

    auto store_pair = [&](int r, int n, float a0, float a1) {
        int t = r & (SEQ - 1);
        if (n < 960) {
            int i = (n & 63) >> 1;
            float c = fcos[t * 32 + i], s = fsin[t * 32 + i];
            float r0 = (a0 * c - a1 * s) * 0.125f;
            float r1 = (a0 * s + a1 * c) * 0.125f;
            __half h0 = __float2half(r0), h1 = __float2half(r1);
            size_t off = (size_t)r * 960 + n;
            *(uint32_t*)(g_q16h + off) = pack2h(h0, h1);
            *(uint32_t*)(g_q16l + off) = pack2h(__float2half(r0 - __half2float(h0)),
                                                __float2half(r1 - __half2float(h1)));
        } else if (n < 1280) {
            int i = (n & 63) >> 1;
            float c = fcos[t * 32 + i], s = fsin[t * 32 + i];
            *(uint32_t*)(g_k16 + (size_t)r * 320 + (n - 960)) =
                pack2h(__float2half(a0 * c - a1 * s), __float2half(a0 * s + a1 * c));
        } else {
            *(uint32_t*)(g_v16 + (size_t)r * 320 + (n - 1280)) =
                pack2h(__float2half(a0), __float2half(a1));
        }
    };

#pragma unroll
    for (int mt = 0; mt < 2; mt++) {
#pragma unroll
        for (int nt = 0; nt < 4; nt++) {
            const int m = m0 + wm * 32 + mt * 16 + (lane >> 2);
            const int n = n0 + wn * 32 + nt * 8 + (lane & 3) * 2;
            store_pair(m,     n, acc[mt][nt][0], acc[mt][nt][1]);
            store_pair(m + 8, n, acc[mt][nt][2], acc[mt][nt][3]);
        }
    }
}

// ---------------- split / transpose helpers ---------------------------------
__global__ void convert_split_kernel(const float* __restrict__ src,
                                     __nv_bfloat16* __restrict__ hi,
                                     __nv_bfloat16* __restrict__ lo, int n) {
    int idx = blockIdx.x * blockDim.x + threadIdx.x;
    if (idx >= n) return;
    float a = src[idx];
    __nv_bfloat16 h = __float2bfloat16(a);
    hi[idx] = h;
    lo[idx] = __float2bfloat16(a - __bfloat162float(h));
}

__global__ void transpose_split_kernel(const float* __restrict__ W,
                                       __nv_bfloat16* __restrict__ hi,
                                       __nv_bfloat16* __restrict__ lo, int K, int N) {
    __shared__ float tile[32][33];
    int k0 = blockIdx.y * 32, n0 = blockIdx.x * 32;
    int tx = threadIdx.x, ty = threadIdx.y;
#pragma unroll
    for (int i = 0; i < 4; i++)
        tile[ty + i * 8][tx] = W[(size_t)(k0 + ty + i * 8) * N + n0 + tx];
    __syncthreads();
#pragma unroll
    for (int i = 0; i < 4; i++) {
        int n = n0 + ty + i * 8;
        float a = tile[tx][ty + i * 8];
        __nv_bfloat16 h = __float2bfloat16(a);
        hi[(size_t)n * K + k0 + tx] = h;
        lo[(size_t)n * K + k0 + tx] = __float2bfloat16(a - __bfloat162float(h));
    }
}

// ---------------- Flash attention on mma.sync fp16 (causal, GQA) --------------
// Q fp16 hi+lo (2-pass QK), K single fp16, V single fp16, P fp16 hi+lo (2-pass PV).
// block: 128 threads (4 warps), 64 q rows; warp w owns rows w*16..w*16+15.
// qt reversed: largest causal tiles scheduled first (wave load balance).
#define AT_PITCH 144
#define AT_QL 9216                  // Q lo staging (stage-0 V area, pre-loop only)
#define AT_VH 9216
#define AT_STAGE 18432
#define ATTN_SMEM (2 * AT_STAGE)    // 36864

__global__ void __launch_bounds__(128)
attn_mma_kernel(const __half* __restrict__ Qhi, const __half* __restrict__ Qlo,
                const __half* __restrict__ Khi, const __half* __restrict__ Vhi,
                __nv_bfloat16* __restrict__ Ohi, __nv_bfloat16* __restrict__ Olo)
{
    extern __shared__ __align__(128) char smem[];
    const uint32_t sbase = smem_to_u32(smem);
    const int tid = threadIdx.x, wid = tid >> 5, lane = tid & 31;
    const int qt = gridDim.x - 1 - blockIdx.x;   // largest tiles first
    const int h = blockIdx.y, b = blockIdx.z;
    const int kvh = h / GQA;

    // ---- stage Q through smem (stage 0 area), extract fragments
    {
        int r = tid >> 1, half = tid & 1;
        size_t gq = ((size_t)(b * SEQ + qt * 64 + r) * NH + h) * HD + half * 32;
        const uint4* ph = (const uint4*)(Qhi + gq);
        const uint4* pl = (const uint4*)(Qlo + gq);
        char* dsth = smem + r * AT_PITCH + half * 64;
        char* dstl = smem + AT_QL + r * AT_PITCH + half * 64;
#pragma unroll
        for (int c = 0; c < 4; c++) { ((uint4*)dsth)[c] = ph[c]; ((uint4*)dstl)[c] = pl[c]; }
    }
    __syncthreads();
    uint32_t qh[4][4], ql[4][4];
    {
        const int a_r = lane & 15, a_cb = (lane >> 4) * 16;
#pragma unroll
        for (int kk = 0; kk < 4; kk++) {
            uint32_t addr = sbase + (wid * 16 + a_r) * AT_PITCH + kk * 32 + a_cb;
            ldsm_x4(qh[kk], addr);
            ldsm_x4(ql[kk], addr + AT_QL);
        }
    }
    __syncthreads();

    auto load_kv = [&](int kt) {
        uint32_t st = sbase + (kt & 1) * AT_STAGE;
        int jr = tid >> 1, cs = (tid & 1) * 4;
        size_t g = ((size_t)(b * SEQ + kt * 64 + jr) * NKV + kvh) * HD + cs * 8;
        uint32_t so = st + jr * AT_PITCH + cs * 16;
#pragma unroll
        for (int c = 0; c < 4; c++) {
            cp_async16(so + c * 16,          Khi + g + c * 8);
            cp_async16(so + AT_VH + c * 16,  Vhi + g + c * 8);
        }
    };

    float O[8][4];
#pragma unroll
    for (int i = 0; i < 8; i++)
#pragma unroll
        for (int j = 0; j < 4; j++) O[i][j] = 0.f;
    float m0 = -CUDART_INF_F, m1 = -CUDART_INF_F;
    float l0 = 0.f, l1 = 0.f;

    load_kv(0); CP_COMMIT();
    if (qt >= 1) load_kv(1);
    CP_COMMIT();

    const int b_rin = lane & 7;
    const int b_mat = lane >> 3;
    const int b_nof = (b_mat >> 1) * 8 + b_rin;
    const int b_kb  = (b_mat & 1) * 16;
    const int v_r   = lane & 15;
    const int v_cb  = (lane >> 4) * 16;
    const int r0loc = wid * 16 + (lane >> 2);

    for (int kt = 0; kt <= qt; kt++) {
        CP_WAIT1();
        __syncthreads();
        const uint32_t st = sbase + (kt & 1) * AT_STAGE;

        // ---- S = Q K^T (2-pass fp16: Qh*K + Ql*K)
        float S[8][4];
#pragma unroll
        for (int i = 0; i < 8; i++)
#pragma unroll
            for (int j = 0; j < 4; j++) S[i][j] = 0.f;

#pragma unroll
        for (int kk = 0; kk < 4; kk++) {
            uint32_t kb[16];
#pragma unroll
            for (int g2 = 0; g2 < 4; g2++) {
                uint32_t addr = st + (g2 * 16 + b_nof) * AT_PITCH + kk * 32 + b_kb;
                ldsm_x4(&kb[g2 * 4], addr);
            }
#pragma unroll
            for (int nt = 0; nt < 8; nt++) {
                mma_f16(S[nt], qh[kk], &kb[nt * 2]);
                mma_f16(S[nt], ql[kk], &kb[nt * 2]);
            }
        }

        // ---- causal mask (diag tile only)
        if (kt == qt) {
#pragma unroll
            for (int nt = 0; nt < 8; nt++) {
                int col = nt * 8 + (lane & 3) * 2;
                if (col     > r0loc)     S[nt][0] = -CUDART_INF_F;
                if (col + 1 > r0loc)     S[nt][1] = -CUDART_INF_F;
                if (col     > r0loc + 8) S[nt][2] = -CUDART_INF_F;
                if (col + 1 > r0loc + 8) S[nt][3] = -CUDART_INF_F;
            }
        }

        // ---- online softmax
        float t0 = -CUDART_INF_F, t1 = -CUDART_INF_F;
#pragma unroll
        for (int nt = 0; nt < 8; nt++) {
            t0 = fmaxf(t0, fmaxf(S[nt][0], S[nt][1]));
            t1 = fmaxf(t1, fmaxf(S[nt][2], S[nt][3]));
        }
        t0 = fmaxf(t0, __shfl_xor_sync(0xffffffffu, t0, 1));
        t0 = fmaxf(t0, __shfl_xor_sync(0xffffffffu, t0, 2));
        t1 = fmaxf(t1, __shfl_xor_sync(0xffffffffu, t1, 1));
        t1 = fmaxf(t1, __shfl_xor_sync(0xffffffffu, t1, 2));
        float mn0 = fmaxf(m0, t0), mn1 = fmaxf(m1, t1);
        float c0 = __expf(m0 - mn0), c1 = __expf(m1 - mn1);
        m0 = mn0; m1 = mn1;

        // ---- P = exp(S - m), split fp16 hi/lo
        uint32_t pkh[4][4], pkl[4][4];
        float la0 = 0.f, la1 = 0.f;
#pragma unroll
        for (int t = 0; t < 4; t++) {
            float p[8];
            p[0] = __expf(S[2*t][0] - mn0);   p[1] = __expf(S[2*t][1] - mn0);
            p[2] = __expf(S[2*t][2] - mn1);   p[3] = __expf(S[2*t][3] - mn1);
            p[4] = __expf(S[2*t+1][0] - mn0); p[5] = __expf(S[2*t+1][1] - mn0);
            p[6] = __expf(S[2*t+1][2] - mn1); p[7] = __expf(S[2*t+1][3] - mn1);
            la0 += p[0] + p[1] + p[4] + p[5];
            la1 += p[2] + p[3] + p[6] + p[7];
            __half hh[8], ll[8];
#pragma unroll
            for (int e = 0; e < 8; e++) {
                hh[e] = __float2half(p[e]);
                ll[e] = __float2half(p[e] - __half2float(hh[e]));
            }
            pkh[t][0] = pack2h(hh[0], hh[1]);  pkl[t][0] = pack2h(ll[0], ll[1]);
            pkh[t][1] = pack2h(hh[2], hh[3]);  pkl[t][1] = pack2h(ll[2], ll[3]);
            pkh[t][2] = pack2h(hh[4], hh[5]);  pkl[t][2] = pack2h(ll[4], ll[5]);
            pkh[t][3] = pack2h(hh[6], hh[7]);  pkl[t][3] = pack2h(ll[6], ll[7]);
        }
        l0 = l0 * c0 + la0;
        l1 = l1 * c1 + la1;

#pragma unroll
        for (int dt = 0; dt < 8; dt++) {
            O[dt][0] *= c0; O[dt][1] *= c0;
            O[dt][2] *= c1; O[dt][3] *= c1;
        }

        // ---- O += P V (2-pass fp16: Ph*V + Pl*V)
#pragma unroll
        for (int t = 0; t < 4; t++) {
            uint32_t vb[16];
#pragma unroll
            for (int db = 0; db < 4; db++) {
                uint32_t addr = st + AT_VH + (t * 16 + v_r) * AT_PITCH + db * 32 + v_cb;
                ldsm_x4_trans(&vb[db * 4], addr);
            }
#pragma unroll
            for (int dt = 0; dt < 8; dt++) {
                mma_f16(O[dt], pkh[t], &vb[dt * 2]);
                mma_f16(O[dt], pkl[t], &vb[dt * 2]);
            }
        }

        __syncthreads();
        if (kt + 2 <= qt) load_kv(kt + 2);
        CP_COMMIT();
    }

    // ---- finalize: normalize, split hi/lo (bf16 for wo GEMM), store
    l0 += __shfl_xor_sync(0xffffffffu, l0, 1);
    l0 += __shfl_xor_sync(0xffffffffu, l0, 2);
    l1 += __shfl_xor_sync(0xffffffffu, l1, 1);
    l1 += __shfl_xor_sync(0xffffffffu, l1, 2);
    float inv0 = 1.f / l0, inv1 = 1.f / l1;

    const int row0 = qt * 64 + r0loc;
#pragma unroll
    for (int dt = 0; dt < 8; dt++) {
        int d = dt * 8 + (lane & 3) * 2;
        size_t o0 = ((size_t)(b * SEQ + row0) * NH + h) * HD + d;
        size_t o1 = o0 + (size_t)8 * NH * HD;
        {
            float a = O[dt][0] * inv0, cc = O[dt][1] * inv0;
            __nv_bfloat16 ah = __float2bfloat16(a), ch = __float2bfloat16(cc);
            *(uint32_t*)(Ohi + o0) = pack2bf(ah, ch);
            *(uint32_t*)(Olo + o0) = pack2bf(__float2bfloat16(a - __bfloat162float(ah)),
                                             __float2bfloat16(cc - __bfloat162float(ch)));
        }
        {
            float a = O[dt][2] * inv1, cc = O[dt][3] * inv1;
            __nv_bfloat16 ah = __float2bfloat16(a), ch = __float2bfloat16(cc);
            *(uint32_t*)(Ohi + o1) = pack2bf(ah, ch);
            *(uint32_t*)(Olo + o1) = pack2bf(__float2bfloat16(a - __bfloat162float(ah)),
                                             __float2bfloat16(cc - __bfloat162float(ch)));
        }
    }
}

// ---------------- launcher ----------------------------------------------------
extern "C" void kernel_launch(void* const* d_in, const int* in_sizes, int n_in,
                              void* d_out, int out_size) {
    const float* x    = (const float*)d_in[0];
    const float* fcos = (const float*)d_in[1];
    const float* fsin = (const float*)d_in[2];
    const float* wq   = (const float*)d_in[3];
    const float* wk   = (const float*)d_in[4];
    const float* wv   = (const float*)d_in[5];
    const float* wo   = (const float*)d_in[6];
    float* out = (float*)d_out;

    __nv_bfloat16 *xhi, *xlo, *ahi, *alo;
    __half *q16h, *q16l, *k16, *v16;
    __nv_bfloat16 *wqkvh, *wqkvl, *woh, *wol;
    cudaGetSymbolAddress((void**)&xhi, g_xhi);
    cudaGetSymbolAddress((void**)&xlo, g_xlo);
    cudaGetSymbolAddress((void**)&ahi, g_ahi);
    cudaGetSymbolAddress((void**)&alo, g_alo);
    cudaGetSymbolAddress((void**)&q16h, g_q16h);
    cudaGetSymbolAddress((void**)&q16l, g_q16l);
    cudaGetSymbolAddress((void**)&k16, g_k16);
    cudaGetSymbolAddress((void**)&v16, g_v16);
    cudaGetSymbolAddress((void**)&wqkvh, g_wqkv_hi);
    cudaGetSymbolAddress((void**)&wqkvl, g_wqkv_lo);
    cudaGetSymbolAddress((void**)&woh, g_wot_hi);
    cudaGetSymbolAddress((void**)&wol, g_wot_lo);

    cudaFuncSetAttribute(gemm_bf16x3_kernel,
                         cudaFuncAttributeMaxDynamicSharedMemorySize, GEMM_SMEM);
    cudaFuncSetAttribute(gemm_qkv_kernel,
                         cudaFuncAttributeMaxDynamicSharedMemorySize, GEMM_SMEM);
    cudaFuncSetAttribute(attn_mma_kernel,
                         cudaFuncAttributeMaxDynamicSharedMemorySize, ATTN_SMEM);

    // input split + weight transposes/splits (wq/wk/wv concatenated rows)
    {
        int n = MTOK * DIM;
        convert_split_kernel<<<(n + 255) / 256, 256>>>(x, xhi, xlo, n);
    }
    transpose_split_kernel<<<dim3(960 / 32, 960 / 32), dim3(32, 8)>>>(
        wq, wqkvh, wqkvl, DIM, 960);
    transpose_split_kernel<<<dim3(320 / 32, 960 / 32), dim3(32, 8)>>>(
        wk, wqkvh + (size_t)960 * 960, wqkvl + (size_t)960 * 960, DIM, 320);
    transpose_split_kernel<<<dim3(320 / 32, 960 / 32), dim3(32, 8)>>>(
        wv, wqkvh + (size_t)1280 * 960, wqkvl + (size_t)1280 * 960, DIM, 320);
    transpose_split_kernel<<<dim3(960 / 32, 960 / 32), dim3(32, 8)>>>(wo, woh, wol, 960, 960);

    // fused QKV projection + RoPE + fp16 split epilogue
    gemm_qkv_kernel<<<dim3(QKV_N / BN, MTOK / BM), 256, GEMM_SMEM>>>(
        xhi, xlo, wqkvh, wqkvl, fcos, fsin);

    // flash attention (fp16 tensor cores) -> bf16 hi/lo attention output
    attn_mma_kernel<<<dim3(SEQ / 64, NH, BATCH), 128, ATTN_SMEM>>>(
        q16h, q16l, k16, v16, ahi, alo);

    // output projection
    gemm_bf16x3_kernel<<<dim3(960 / BN, MTOK / BM), 256, GEMM_SMEM>>>(
        ahi, alo, woh, wol, out, MTOK, 960, 960);
}

// round 12
// speedup vs baseline: 2.4757x; 1.2652x over previous
#include <cuda_runtime.h>
#include <cuda_bf16.h>
#include <cuda_fp16.h>
#include <math_constants.h>
#include <cstdint>

// Problem constants
#define BATCH 4
#define SEQ 2048
#define DIM 960
#define NH 15
#define NKV 5
#define HD 64
#define GQA 3
#define MTOK (BATCH*SEQ)   // 8192
#define QKV_N 1600         // 960 q + 320 k + 320 v

#define INV32 0.03125f     // epilogue rescale for x32 weight scaling

// ---------------- scratch (device globals; no allocations) ----------------
__device__ __half g_x16[(size_t)MTOK * DIM];
__device__ __half g_o16[(size_t)MTOK * DIM];          // attention out (fp16 single)
__device__ __half g_q16h[(size_t)MTOK * NH * HD];
__device__ __half g_q16l[(size_t)MTOK * NH * HD];
__device__ __half g_k16[(size_t)MTOK * NKV * HD];
__device__ __half g_v16[(size_t)MTOK * NKV * HD];
__device__ __half g_wqkv_hi[(size_t)QKV_N * 960];     // x32-scaled, transposed
__device__ __half g_wqkv_lo[(size_t)QKV_N * 960];
__device__ __half g_wot_hi[(size_t)960 * 960];        // x32-scaled, transposed
__device__ __half g_wot_lo[(size_t)960 * 960];

// ---------------- small PTX helpers ------------------------------------------
__device__ __forceinline__ uint32_t smem_to_u32(const void* p) {
    uint32_t a;
    asm("{ .reg .u64 t; cvta.to.shared.u64 t, %1; cvt.u32.u64 %0, t; }" : "=r"(a) : "l"(p));
    return a;
}
__device__ __forceinline__ void cp_async16(uint32_t saddr, const void* gptr) {
    asm volatile("cp.async.cg.shared.global [%0], [%1], 16;" :: "r"(saddr), "l"(gptr));
}
#define CP_COMMIT() asm volatile("cp.async.commit_group;" ::: "memory")
#define CP_WAIT1()  asm volatile("cp.async.wait_group 1;" ::: "memory")

__device__ __forceinline__ void ldsm_x4(uint32_t* r, uint32_t addr) {
    asm volatile("ldmatrix.sync.aligned.m8n8.x4.shared.b16 {%0,%1,%2,%3}, [%4];"
                 : "=r"(r[0]), "=r"(r[1]), "=r"(r[2]), "=r"(r[3]) : "r"(addr));
}
__device__ __forceinline__ void ldsm_x4_trans(uint32_t* r, uint32_t addr) {
    asm volatile("ldmatrix.sync.aligned.m8n8.x4.trans.shared.b16 {%0,%1,%2,%3}, [%4];"
                 : "=r"(r[0]), "=r"(r[1]), "=r"(r[2]), "=r"(r[3]) : "r"(addr));
}
__device__ __forceinline__ void mma_f16(float* d, const uint32_t* a, const uint32_t* b) {
    asm volatile(
        "mma.sync.aligned.m16n8k16.row.col.f32.f16.f16.f32 "
        "{%0,%1,%2,%3}, {%4,%5,%6,%7}, {%8,%9}, {%0,%1,%2,%3};"
        : "+f"(d[0]), "+f"(d[1]), "+f"(d[2]), "+f"(d[3])
        : "r"(a[0]), "r"(a[1]), "r"(a[2]), "r"(a[3]), "r"(b[0]), "r"(b[1]));
}
__device__ __forceinline__ uint32_t pack2h(__half a, __half b) {
    __half2 t = __halves2half2(a, b);
    return *(uint32_t*)&t;
}

// ---------------- fp16x2 GEMM core macros -------------------------------------
// C[M,N] = (1/32)*A[M,K]@B^T, A single fp16, B = x32-scaled weights fp16 hi+lo.
#define BM 128
#define BN 64
#define BK 32
#define NSTAGE 3
#define A_PITCH 80
#define SB_H (128 * A_PITCH)                 // A single: 128 rows x 80B
#define SB_L (SB_H + 64 * A_PITCH)
#define STAGE_BYTES (SB_L + 64 * A_PITCH)    // 20480
#define GEMM_SMEM (NSTAGE * STAGE_BYTES)     // 61440

#define GEMM_MAINLOOP(A16, Bhi, Blo, K)                                              \
    const uint32_t sbase = smem_to_u32(smem);                                        \
    const int tid  = threadIdx.x;                                                    \
    const int wid  = tid >> 5;                                                       \
    const int lane = tid & 31;                                                       \
    const int m0 = blockIdx.y * BM;                                                  \
    const int n0 = blockIdx.x * BN;                                                  \
    const int wm = wid >> 1;                                                         \
    const int wn = wid & 1;                                                          \
    const int nchunk = (K) / BK;                                                     \
    const int arow = tid >> 1;                                                       \
    const int acol = (tid & 1) * 2;                                                  \
    const int brow = tid >> 2;                                                       \
    const int bcol = tid & 3;                                                        \
    auto load_stage = [&](int ci, int s) {                                           \
        const uint32_t st = sbase + s * STAGE_BYTES;                                 \
        const int k0 = ci * BK;                                                      \
        {                                                                            \
            const size_t go = (size_t)(m0 + arow) * (K) + k0 + acol * 8;             \
            const uint32_t so = st + arow * A_PITCH + acol * 16;                     \
            cp_async16(so,      (A16) + go);                                         \
            cp_async16(so + 16, (A16) + go + 8);                                     \
        }                                                                            \
        {                                                                            \
            const size_t go = (size_t)(n0 + brow) * (K) + k0 + bcol * 8;             \
            const uint32_t so = st + SB_H + brow * A_PITCH + bcol * 16;              \
            cp_async16(so,                (Bhi) + go);                               \
            cp_async16(so + 64 * A_PITCH, (Blo) + go);                               \
        }                                                                            \
    };                                                                               \
    float acc[2][4][4];                                                              \
    _Pragma("unroll")                                                                \
    for (int i = 0; i < 2; i++)                                                      \
        _Pragma("unroll")                                                            \
        for (int j = 0; j < 4; j++)                                                  \
            _Pragma("unroll")                                                        \
            for (int v = 0; v < 4; v++) acc[i][j][v] = 0.f;                          \
    load_stage(0, 0); CP_COMMIT();                                                   \
    load_stage(1, 1); CP_COMMIT();                                                   \
    const int a_r   = lane & 15;                                                     \
    const int a_cb  = (lane >> 4) * 16;                                              \
    const int b_mat = lane >> 3;                                                     \
    const int b_rin = lane & 7;                                                      \
    const int b_nof = (b_mat >> 1) * 8 + b_rin;                                      \
    const int b_kb  = (b_mat & 1) * 16;                                              \
    for (int i = 0; i < nchunk; i++) {                                               \
        CP_WAIT1();                                                                  \
        __syncthreads();                                                             \
        if (i + 2 < nchunk) load_stage(i + 2, (i + 2) % NSTAGE);                     \
        CP_COMMIT();                                                                 \
        const uint32_t st = sbase + (i % NSTAGE) * STAGE_BYTES;                      \
        _Pragma("unroll")                                                            \
        for (int kk = 0; kk < 2; kk++) {                                             \
            const int kbyte = kk * 32;                                               \
            uint32_t ah[2][4], bh[8], bl[8];                                         \
            _Pragma("unroll")                                                        \
            for (int mt = 0; mt < 2; mt++) {                                         \
                uint32_t addr = st + (wm * 32 + mt * 16 + a_r) * A_PITCH + kbyte + a_cb; \
                ldsm_x4(ah[mt], addr);                                               \
            }                                                                        \
            _Pragma("unroll")                                                        \
            for (int hh = 0; hh < 2; hh++) {                                         \
                uint32_t addr = st + SB_H + (wn * 32 + hh * 16 + b_nof) * A_PITCH + kbyte + b_kb; \
                ldsm_x4(&bh[hh * 4], addr);                                          \
                ldsm_x4(&bl[hh * 4], addr + 64 * A_PITCH);                           \
            }                                                                        \
            _Pragma("unroll")                                                        \
            for (int mt = 0; mt < 2; mt++)                                           \
                _Pragma("unroll")                                                    \
                for (int nt = 0; nt < 4; nt++) {                                     \
                    mma_f16(acc[mt][nt], ah[mt], &bh[nt * 2]);                       \
                    mma_f16(acc[mt][nt], ah[mt], &bl[nt * 2]);                       \
                }                                                                    \
        }                                                                            \
        __syncthreads();                                                             \
    }

// ---------------- output-proj GEMM (fp32 epilogue, /32) -----------------------
__global__ void __launch_bounds__(256, 2)
gemm_out_kernel(const __half* __restrict__ A16,
                const __half* __restrict__ Bhi,
                const __half* __restrict__ Blo,
                float* __restrict__ C, int M, int N, int K)
{
    extern __shared__ __align__(128) char smem[];
    GEMM_MAINLOOP(A16, Bhi, Blo, K)
#pragma unroll
    for (int mt = 0; mt < 2; mt++) {
#pragma unroll
        for (int nt = 0; nt < 4; nt++) {
            const int m = m0 + wm * 32 + mt * 16 + (lane >> 2);
            const int n = n0 + wn * 32 + nt * 8 + (lane & 3) * 2;
            *(float2*)&C[(size_t)m * N + n] =
                make_float2(acc[mt][nt][0] * INV32, acc[mt][nt][1] * INV32);
            *(float2*)&C[(size_t)(m + 8) * N + n] =
                make_float2(acc[mt][nt][2] * INV32, acc[mt][nt][3] * INV32);
        }
    }
}

// ---------------- fused QKV GEMM with RoPE+split epilogue ---------------------
// N=1600: cols [0,960) -> q (rope, /32*0.125, fp16 hi+lo), [960,1280) -> k
// (rope, /32, fp16), [1280,1600) -> v (/32, fp16). Outputs via device symbols.
__global__ void __launch_bounds__(256, 2)
gemm_qkv_kernel(const __half* __restrict__ A16,
                const __half* __restrict__ Bhi,
                const __half* __restrict__ Blo,
                const float* __restrict__ fcos, const float* __restrict__ fsin)
{
    extern __shared__ __align__(128) char smem[];
    GEMM_MAINLOOP(A16, Bhi, Blo, DIM)

    auto store_pair = [&](int r, int n, float a0, float a1) {
        int t = r & (SEQ - 1);
        a0 *= INV32; a1 *= INV32;
        if (n < 960) {
            int i = (n & 63) >> 1;
            float c = fcos[t * 32 + i], s = fsin[t * 32 + i];
            float r0 = (a0 * c - a1 * s) * 0.125f;
            float r1 = (a0 * s + a1 * c) * 0.125f;
            __half h0 = __float2half(r0), h1 = __float2half(r1);
            size_t off = (size_t)r * 960 + n;
            *(uint32_t*)(g_q16h + off) = pack2h(h0, h1);
            *(uint32_t*)(g_q16l + off) = pack2h(__float2half(r0 - __half2float(h0)),
                                                __float2half(r1 - __half2float(h1)));
        } else if (n < 1280) {
            int i = (n & 63) >> 1;
            float c = fcos[t * 32 + i], s = fsin[t * 32 + i];
            *(uint32_t*)(g_k16 + (size_t)r * 320 + (n - 960)) =
                pack2h(__float2half(a0 * c - a1 * s), __float2half(a0 * s + a1 * c));
        } else {
            *(uint32_t*)(g_v16 + (size_t)r * 320 + (n - 1280)) =
                pack2h(__float2half(a0), __float2half(a1));
        }
    };

#pragma unroll
    for (int mt = 0; mt < 2; mt++) {
#pragma unroll
        for (int nt = 0; nt < 4; nt++) {
            const int m = m0 + wm * 32 + mt * 16 + (lane >> 2);
            const int n = n0 + wn * 32 + nt * 8 + (lane & 3) * 2;
            store_pair(m,     n, acc[mt][nt][0], acc[mt][nt][1]);
            store_pair(m + 8, n, acc[mt][nt][2], acc[mt][nt][3]);
        }
    }
}

// ---------------- convert / transpose helpers ---------------------------------
__global__ void convert_f16_kernel(const float* __restrict__ src,
                                   __half* __restrict__ dst, int n) {
    int idx = blockIdx.x * blockDim.x + threadIdx.x;
    if (idx >= n) return;
    dst[idx] = __float2half(src[idx]);
}

// W[K][N] -> Wt_hi/lo[n*K + k], scaled x32 (keeps fp16 residuals normal-range)
__global__ void transpose_split_f16_kernel(const float* __restrict__ W,
                                           __half* __restrict__ hi,
                                           __half* __restrict__ lo, int K, int N) {
    __shared__ float tile[32][33];
    int k0 = blockIdx.y * 32, n0 = blockIdx.x * 32;
    int tx = threadIdx.x, ty = threadIdx.y;
#pragma unroll
    for (int i = 0; i < 4; i++)
        tile[ty + i * 8][tx] = W[(size_t)(k0 + ty + i * 8) * N + n0 + tx];
    __syncthreads();
#pragma unroll
    for (int i = 0; i < 4; i++) {
        int n = n0 + ty + i * 8;
        float a = tile[tx][ty + i * 8] * 32.0f;
        __half h = __float2half(a);
        hi[(size_t)n * K + k0 + tx] = h;
        lo[(size_t)n * K + k0 + tx] = __float2half(a - __half2float(h));
    }
}

// ---------------- Flash attention on mma.sync fp16 (causal, GQA) --------------
// Q fp16 hi+lo (2-pass QK), K single fp16, V single fp16, P fp16 hi+lo (2-pass PV).
// block: 128 threads (4 warps), 64 q rows; qt reversed for wave balance.
#define AT_PITCH 144
#define AT_QL 9216
#define AT_VH 9216
#define AT_STAGE 18432
#define ATTN_SMEM (2 * AT_STAGE)    // 36864

__global__ void __launch_bounds__(128)
attn_mma_kernel(const __half* __restrict__ Qhi, const __half* __restrict__ Qlo,
                const __half* __restrict__ Khi, const __half* __restrict__ Vhi,
                __half* __restrict__ O16)
{
    extern __shared__ __align__(128) char smem[];
    const uint32_t sbase = smem_to_u32(smem);
    const int tid = threadIdx.x, wid = tid >> 5, lane = tid & 31;
    const int qt = gridDim.x - 1 - blockIdx.x;
    const int h = blockIdx.y, b = blockIdx.z;
    const int kvh = h / GQA;

    // ---- stage Q through smem (stage 0 area), extract fragments
    {
        int r = tid >> 1, half = tid & 1;
        size_t gq = ((size_t)(b * SEQ + qt * 64 + r) * NH + h) * HD + half * 32;
        const uint4* ph = (const uint4*)(Qhi + gq);
        const uint4* pl = (const uint4*)(Qlo + gq);
        char* dsth = smem + r * AT_PITCH + half * 64;
        char* dstl = smem + AT_QL + r * AT_PITCH + half * 64;
#pragma unroll
        for (int c = 0; c < 4; c++) { ((uint4*)dsth)[c] = ph[c]; ((uint4*)dstl)[c] = pl[c]; }
    }
    __syncthreads();
    uint32_t qh[4][4], ql[4][4];
    {
        const int a_r = lane & 15, a_cb = (lane >> 4) * 16;
#pragma unroll
        for (int kk = 0; kk < 4; kk++) {
            uint32_t addr = sbase + (wid * 16 + a_r) * AT_PITCH + kk * 32 + a_cb;
            ldsm_x4(qh[kk], addr);
            ldsm_x4(ql[kk], addr + AT_QL);
        }
    }
    __syncthreads();

    auto load_kv = [&](int kt) {
        uint32_t st = sbase + (kt & 1) * AT_STAGE;
        int jr = tid >> 1, cs = (tid & 1) * 4;
        size_t g = ((size_t)(b * SEQ + kt * 64 + jr) * NKV + kvh) * HD + cs * 8;
        uint32_t so = st + jr * AT_PITCH + cs * 16;
#pragma unroll
        for (int c = 0; c < 4; c++) {
            cp_async16(so + c * 16,          Khi + g + c * 8);
            cp_async16(so + AT_VH + c * 16,  Vhi + g + c * 8);
        }
    };

    float O[8][4];
#pragma unroll
    for (int i = 0; i < 8; i++)
#pragma unroll
        for (int j = 0; j < 4; j++) O[i][j] = 0.f;
    float m0 = -CUDART_INF_F, m1 = -CUDART_INF_F;
    float l0 = 0.f, l1 = 0.f;

    load_kv(0); CP_COMMIT();
    if (qt >= 1) load_kv(1);
    CP_COMMIT();

    const int b_rin = lane & 7;
    const int b_mat = lane >> 3;
    const int b_nof = (b_mat >> 1) * 8 + b_rin;
    const int b_kb  = (b_mat & 1) * 16;
    const int v_r   = lane & 15;
    const int v_cb  = (lane >> 4) * 16;
    const int r0loc = wid * 16 + (lane >> 2);

    for (int kt = 0; kt <= qt; kt++) {
        CP_WAIT1();
        __syncthreads();
        const uint32_t st = sbase + (kt & 1) * AT_STAGE;

        // ---- S = Q K^T (2-pass fp16)
        float S[8][4];
#pragma unroll
        for (int i = 0; i < 8; i++)
#pragma unroll
            for (int j = 0; j < 4; j++) S[i][j] = 0.f;

#pragma unroll
        for (int kk = 0; kk < 4; kk++) {
            uint32_t kb[16];
#pragma unroll
            for (int g2 = 0; g2 < 4; g2++) {
                uint32_t addr = st + (g2 * 16 + b_nof) * AT_PITCH + kk * 32 + b_kb;
                ldsm_x4(&kb[g2 * 4], addr);
            }
#pragma unroll
            for (int nt = 0; nt < 8; nt++) {
                mma_f16(S[nt], qh[kk], &kb[nt * 2]);
                mma_f16(S[nt], ql[kk], &kb[nt * 2]);
            }
        }

        // ---- causal mask (diag tile only)
        if (kt == qt) {
#pragma unroll
            for (int nt = 0; nt < 8; nt++) {
                int col = nt * 8 + (lane & 3) * 2;
                if (col     > r0loc)     S[nt][0] = -CUDART_INF_F;
                if (col + 1 > r0loc)     S[nt][1] = -CUDART_INF_F;
                if (col     > r0loc + 8) S[nt][2] = -CUDART_INF_F;
                if (col + 1 > r0loc + 8) S[nt][3] = -CUDART_INF_F;
            }
        }

        // ---- online softmax
        float t0 = -CUDART_INF_F, t1 = -CUDART_INF_F;
#pragma unroll
        for (int nt = 0; nt < 8; nt++) {
            t0 = fmaxf(t0, fmaxf(S[nt][0], S[nt][1]));
            t1 = fmaxf(t1, fmaxf(S[nt][2], S[nt][3]));
        }
        t0 = fmaxf(t0, __shfl_xor_sync(0xffffffffu, t0, 1));
        t0 = fmaxf(t0, __shfl_xor_sync(0xffffffffu, t0, 2));
        t1 = fmaxf(t1, __shfl_xor_sync(0xffffffffu, t1, 1));
        t1 = fmaxf(t1, __shfl_xor_sync(0xffffffffu, t1, 2));
        float mn0 = fmaxf(m0, t0), mn1 = fmaxf(m1, t1);
        float c0 = __expf(m0 - mn0), c1 = __expf(m1 - mn1);
        m0 = mn0; m1 = mn1;

        // ---- P = exp(S - m), split fp16 hi/lo
        uint32_t pkh[4][4], pkl[4][4];
        float la0 = 0.f, la1 = 0.f;
#pragma unroll
        for (int t = 0; t < 4; t++) {
            float p[8];
            p[0] = __expf(S[2*t][0] - mn0);   p[1] = __expf(S[2*t][1] - mn0);
            p[2] = __expf(S[2*t][2] - mn1);   p[3] = __expf(S[2*t][3] - mn1);
            p[4] = __expf(S[2*t+1][0] - mn0); p[5] = __expf(S[2*t+1][1] - mn0);
            p[6] = __expf(S[2*t+1][2] - mn1); p[7] = __expf(S[2*t+1][3] - mn1);
            la0 += p[0] + p[1] + p[4] + p[5];
            la1 += p[2] + p[3] + p[6] + p[7];
            __half hh[8], ll[8];
#pragma unroll
            for (int e = 0; e < 8; e++) {
                hh[e] = __float2half(p[e]);
                ll[e] = __float2half(p[e] - __half2float(hh[e]));
            }
            pkh[t][0] = pack2h(hh[0], hh[1]);  pkl[t][0] = pack2h(ll[0], ll[1]);
            pkh[t][1] = pack2h(hh[2], hh[3]);  pkl[t][1] = pack2h(ll[2], ll[3]);
            pkh[t][2] = pack2h(hh[4], hh[5]);  pkl[t][2] = pack2h(ll[4], ll[5]);
            pkh[t][3] = pack2h(hh[6], hh[7]);  pkl[t][3] = pack2h(ll[6], ll[7]);
        }
        l0 = l0 * c0 + la0;
        l1 = l1 * c1 + la1;

#pragma unroll
        for (int dt = 0; dt < 8; dt++) {
            O[dt][0] *= c0; O[dt][1] *= c0;
            O[dt][2] *= c1; O[dt][3] *= c1;
        }

        // ---- O += P V (2-pass fp16)
#pragma unroll
        for (int t = 0; t < 4; t++) {
            uint32_t vb[16];
#pragma unroll
            for (int db = 0; db < 4; db++) {
                uint32_t addr = st + AT_VH + (t * 16 + v_r) * AT_PITCH + db * 32 + v_cb;
                ldsm_x4_trans(&vb[db * 4], addr);
            }
#pragma unroll
            for (int dt = 0; dt < 8; dt++) {
                mma_f16(O[dt], pkh[t], &vb[dt * 2]);
                mma_f16(O[dt], pkl[t], &vb[dt * 2]);
            }
        }

        __syncthreads();
        if (kt + 2 <= qt) load_kv(kt + 2);
        CP_COMMIT();
    }

    // ---- finalize: normalize, store fp16 single (out-proj A operand)
    l0 += __shfl_xor_sync(0xffffffffu, l0, 1);
    l0 += __shfl_xor_sync(0xffffffffu, l0, 2);
    l1 += __shfl_xor_sync(0xffffffffu, l1, 1);
    l1 += __shfl_xor_sync(0xffffffffu, l1, 2);
    float inv0 = 1.f / l0, inv1 = 1.f / l1;

    const int row0 = qt * 64 + r0loc;
#pragma unroll
    for (int dt = 0; dt < 8; dt++) {
        int d = dt * 8 + (lane & 3) * 2;
        size_t o0 = ((size_t)(b * SEQ + row0) * NH + h) * HD + d;
        size_t o1 = o0 + (size_t)8 * NH * HD;
        *(uint32_t*)(O16 + o0) = pack2h(__float2half(O[dt][0] * inv0),
                                        __float2half(O[dt][1] * inv0));
        *(uint32_t*)(O16 + o1) = pack2h(__float2half(O[dt][2] * inv1),
                                        __float2half(O[dt][3] * inv1));
    }
}

// ---------------- launcher ----------------------------------------------------
extern "C" void kernel_launch(void* const* d_in, const int* in_sizes, int n_in,
                              void* d_out, int out_size) {
    const float* x    = (const float*)d_in[0];
    const float* fcos = (const float*)d_in[1];
    const float* fsin = (const float*)d_in[2];
    const float* wq   = (const float*)d_in[3];
    const float* wk   = (const float*)d_in[4];
    const float* wv   = (const float*)d_in[5];
    const float* wo   = (const float*)d_in[6];
    float* out = (float*)d_out;

    __half *x16, *o16, *q16h, *q16l, *k16, *v16;
    __half *wqkvh, *wqkvl, *woh, *wol;
    cudaGetSymbolAddress((void**)&x16, g_x16);
    cudaGetSymbolAddress((void**)&o16, g_o16);
    cudaGetSymbolAddress((void**)&q16h, g_q16h);
    cudaGetSymbolAddress((void**)&q16l, g_q16l);
    cudaGetSymbolAddress((void**)&k16, g_k16);
    cudaGetSymbolAddress((void**)&v16, g_v16);
    cudaGetSymbolAddress((void**)&wqkvh, g_wqkv_hi);
    cudaGetSymbolAddress((void**)&wqkvl, g_wqkv_lo);
    cudaGetSymbolAddress((void**)&woh, g_wot_hi);
    cudaGetSymbolAddress((void**)&wol, g_wot_lo);

    cudaFuncSetAttribute(gemm_out_kernel,
                         cudaFuncAttributeMaxDynamicSharedMemorySize, GEMM_SMEM);
    cudaFuncSetAttribute(gemm_qkv_kernel,
                         cudaFuncAttributeMaxDynamicSharedMemorySize, GEMM_SMEM);
    cudaFuncSetAttribute(attn_mma_kernel,
                         cudaFuncAttributeMaxDynamicSharedMemorySize, ATTN_SMEM);

    // input -> fp16; weight transposes/splits (x32-scaled, concatenated rows)
    {
        int n = MTOK * DIM;
        convert_f16_kernel<<<(n + 255) / 256, 256>>>(x, x16, n);
    }
    transpose_split_f16_kernel<<<dim3(960 / 32, 960 / 32), dim3(32, 8)>>>(
        wq, wqkvh, wqkvl, DIM, 960);
    transpose_split_f16_kernel<<<dim3(320 / 32, 960 / 32), dim3(32, 8)>>>(
        wk, wqkvh + (size_t)960 * 960, wqkvl + (size_t)960 * 960, DIM, 320);
    transpose_split_f16_kernel<<<dim3(320 / 32, 960 / 32), dim3(32, 8)>>>(
        wv, wqkvh + (size_t)1280 * 960, wqkvl + (size_t)1280 * 960, DIM, 320);
    transpose_split_f16_kernel<<<dim3(960 / 32, 960 / 32), dim3(32, 8)>>>(
        wo, woh, wol, 960, 960);

    // fused QKV projection + RoPE + fp16 split epilogue
    gemm_qkv_kernel<<<dim3(QKV_N / BN, MTOK / BM), 256, GEMM_SMEM>>>(
        x16, wqkvh, wqkvl, fcos, fsin);

    // flash attention (fp16 tensor cores) -> fp16 attention output
    attn_mma_kernel<<<dim3(SEQ / 64, NH, BATCH), 128, ATTN_SMEM>>>(
        q16h, q16l, k16, v16, o16);

    // output projection
    gemm_out_kernel<<<dim3(960 / BN, MTOK / BM), 256, GEMM_SMEM>>>(
        o16, woh, wol, out, MTOK, 960, 960);
}

// round 13
// speedup vs baseline: 3.2283x; 1.3040x over previous
#include <cuda_runtime.h>
#include <cuda_bf16.h>
#include <cuda_fp16.h>
#include <math_constants.h>
#include <cstdint>

// Problem constants
#define BATCH 4
#define SEQ 2048
#define DIM 960
#define NH 15
#define NKV 5
#define HD 64
#define GQA 3
#define MTOK (BATCH*SEQ)   // 8192
#define QKV_N 1600         // 960 q + 320 k + 320 v

// ---------------- scratch (device globals; no allocations) ----------------
__device__ __half g_x16[(size_t)MTOK * DIM];
__device__ __half g_o16[(size_t)MTOK * DIM];          // attention out (fp16)
__device__ __half g_q16h[(size_t)MTOK * NH * HD];
__device__ __half g_q16l[(size_t)MTOK * NH * HD];
__device__ __half g_k16[(size_t)MTOK * NKV * HD];
__device__ __half g_v16[(size_t)MTOK * NKV * HD];
__device__ __half g_wqkv[(size_t)QKV_N * 960];        // transposed fp16
__device__ __half g_wot[(size_t)960 * 960];           // transposed fp16

// ---------------- small PTX helpers ------------------------------------------
__device__ __forceinline__ uint32_t smem_to_u32(const void* p) {
    uint32_t a;
    asm("{ .reg .u64 t; cvta.to.shared.u64 t, %1; cvt.u32.u64 %0, t; }" : "=r"(a) : "l"(p));
    return a;
}
__device__ __forceinline__ void cp_async16(uint32_t saddr, const void* gptr) {
    asm volatile("cp.async.cg.shared.global [%0], [%1], 16;" :: "r"(saddr), "l"(gptr));
}
#define CP_COMMIT() asm volatile("cp.async.commit_group;" ::: "memory")
#define CP_WAIT1()  asm volatile("cp.async.wait_group 1;" ::: "memory")

__device__ __forceinline__ void ldsm_x4(uint32_t* r, uint32_t addr) {
    asm volatile("ldmatrix.sync.aligned.m8n8.x4.shared.b16 {%0,%1,%2,%3}, [%4];"
                 : "=r"(r[0]), "=r"(r[1]), "=r"(r[2]), "=r"(r[3]) : "r"(addr));
}
__device__ __forceinline__ void ldsm_x4_trans(uint32_t* r, uint32_t addr) {
    asm volatile("ldmatrix.sync.aligned.m8n8.x4.trans.shared.b16 {%0,%1,%2,%3}, [%4];"
                 : "=r"(r[0]), "=r"(r[1]), "=r"(r[2]), "=r"(r[3]) : "r"(addr));
}
__device__ __forceinline__ void mma_f16(float* d, const uint32_t* a, const uint32_t* b) {
    asm volatile(
        "mma.sync.aligned.m16n8k16.row.col.f32.f16.f16.f32 "
        "{%0,%1,%2,%3}, {%4,%5,%6,%7}, {%8,%9}, {%0,%1,%2,%3};"
        : "+f"(d[0]), "+f"(d[1]), "+f"(d[2]), "+f"(d[3])
        : "r"(a[0]), "r"(a[1]), "r"(a[2]), "r"(a[3]), "r"(b[0]), "r"(b[1]));
}
__device__ __forceinline__ uint32_t pack2h(__half a, __half b) {
    __half2 t = __halves2half2(a, b);
    return *(uint32_t*)&t;
}

// ---------------- plain fp16 GEMM core macros ---------------------------------
// C[M,N] = A[M,K]@B^T, both single fp16, fp32 accumulate.
#define BM 128
#define BN 64
#define BK 32
#define NSTAGE 3
#define A_PITCH 80
#define SB_OFF (128 * A_PITCH)               // B tile after A tile
#define STAGE_BYTES (SB_OFF + 64 * A_PITCH)  // 15360
#define GEMM_SMEM (NSTAGE * STAGE_BYTES)     // 46080

#define GEMM_MAINLOOP(A16, B16, K)                                                   \
    const uint32_t sbase = smem_to_u32(smem);                                        \
    const int tid  = threadIdx.x;                                                    \
    const int wid  = tid >> 5;                                                       \
    const int lane = tid & 31;                                                       \
    const int m0 = blockIdx.y * BM;                                                  \
    const int n0 = blockIdx.x * BN;                                                  \
    const int wm = wid >> 1;                                                         \
    const int wn = wid & 1;                                                          \
    const int nchunk = (K) / BK;                                                     \
    const int arow = tid >> 1;                                                       \
    const int acol = (tid & 1) * 2;                                                  \
    const int brow = tid >> 2;                                                       \
    const int bcol = tid & 3;                                                        \
    auto load_stage = [&](int ci, int s) {                                           \
        const uint32_t st = sbase + s * STAGE_BYTES;                                 \
        const int k0 = ci * BK;                                                      \
        {                                                                            \
            const size_t go = (size_t)(m0 + arow) * (K) + k0 + acol * 8;             \
            const uint32_t so = st + arow * A_PITCH + acol * 16;                     \
            cp_async16(so,      (A16) + go);                                         \
            cp_async16(so + 16, (A16) + go + 8);                                     \
        }                                                                            \
        {                                                                            \
            const size_t go = (size_t)(n0 + brow) * (K) + k0 + bcol * 8;             \
            const uint32_t so = st + SB_OFF + brow * A_PITCH + bcol * 16;            \
            cp_async16(so, (B16) + go);                                              \
        }                                                                            \
    };                                                                               \
    float acc[2][4][4];                                                              \
    _Pragma("unroll")                                                                \
    for (int i = 0; i < 2; i++)                                                      \
        _Pragma("unroll")                                                            \
        for (int j = 0; j < 4; j++)                                                  \
            _Pragma("unroll")                                                        \
            for (int v = 0; v < 4; v++) acc[i][j][v] = 0.f;                          \
    load_stage(0, 0); CP_COMMIT();                                                   \
    load_stage(1, 1); CP_COMMIT();                                                   \
    const int a_r   = lane & 15;                                                     \
    const int a_cb  = (lane >> 4) * 16;                                              \
    const int b_mat = lane >> 3;                                                     \
    const int b_rin = lane & 7;                                                      \
    const int b_nof = (b_mat >> 1) * 8 + b_rin;                                      \
    const int b_kb  = (b_mat & 1) * 16;                                              \
    for (int i = 0; i < nchunk; i++) {                                               \
        CP_WAIT1();                                                                  \
        __syncthreads();                                                             \
        if (i + 2 < nchunk) load_stage(i + 2, (i + 2) % NSTAGE);                     \
        CP_COMMIT();                                                                 \
        const uint32_t st = sbase + (i % NSTAGE) * STAGE_BYTES;                      \
        _Pragma("unroll")                                                            \
        for (int kk = 0; kk < 2; kk++) {                                             \
            const int kbyte = kk * 32;                                               \
            uint32_t ah[2][4], bh[8];                                                \
            _Pragma("unroll")                                                        \
            for (int mt = 0; mt < 2; mt++) {                                         \
                uint32_t addr = st + (wm * 32 + mt * 16 + a_r) * A_PITCH + kbyte + a_cb; \
                ldsm_x4(ah[mt], addr);                                               \
            }                                                                        \
            _Pragma("unroll")                                                        \
            for (int hh = 0; hh < 2; hh++) {                                         \
                uint32_t addr = st + SB_OFF + (wn * 32 + hh * 16 + b_nof) * A_PITCH + kbyte + b_kb; \
                ldsm_x4(&bh[hh * 4], addr);                                          \
            }                                                                        \
            _Pragma("unroll")                                                        \
            for (int mt = 0; mt < 2; mt++)                                           \
                _Pragma("unroll")                                                    \
                for (int nt = 0; nt < 4; nt++)                                       \
                    mma_f16(acc[mt][nt], ah[mt], &bh[nt * 2]);                       \
        }                                                                            \
        __syncthreads();                                                             \
    }

// ---------------- output-proj GEMM (fp32 epilogue) ----------------------------
__global__ void __launch_bounds__(256, 2)
gemm_out_kernel(const __half* __restrict__ A16,
                const __half* __restrict__ B16,
                float* __restrict__ C, int M, int N, int K)
{
    extern __shared__ __align__(128) char smem[];
    GEMM_MAINLOOP(A16, B16, K)
#pragma unroll
    for (int mt = 0; mt < 2; mt++) {
#pragma unroll
        for (int nt = 0; nt < 4; nt++) {
            const int m = m0 + wm * 32 + mt * 16 + (lane >> 2);
            const int n = n0 + wn * 32 + nt * 8 + (lane & 3) * 2;
            *(float2*)&C[(size_t)m * N + n]       = make_float2(acc[mt][nt][0], acc[mt][nt][1]);
            *(float2*)&C[(size_t)(m + 8) * N + n] = make_float2(acc[mt][nt][2], acc[mt][nt][3]);
        }
    }
}

// ---------------- fused QKV GEMM with RoPE+split epilogue ---------------------
// N=1600: cols [0,960) -> q (rope, *0.125, fp16 hi+lo), [960,1280) -> k (rope),
// [1280,1600) -> v. Outputs via device symbols.
__global__ void __launch_bounds__(256, 2)
gemm_qkv_kernel(const __half* __restrict__ A16,
                const __half* __restrict__ B16,
                const float* __restrict__ fcos, const float* __restrict__ fsin)
{
    extern __shared__ __align__(128) char smem[];
    GEMM_MAINLOOP(A16, B16, DIM)

    auto store_pair = [&](int r, int n, float a0, float a1) {
        int t = r & (SEQ - 1);
        if (n < 960) {
            int i = (n & 63) >> 1;
            float c = fcos[t * 32 + i], s = fsin[t * 32 + i];
            float r0 = (a0 * c - a1 * s) * 0.125f;
            float r1 = (a0 * s + a1 * c) * 0.125f;
            __half h0 = __float2half(r0), h1 = __float2half(r1);
            size_t off = (size_t)r * 960 + n;
            *(uint32_t*)(g_q16h + off) = pack2h(h0, h1);
            *(uint32_t*)(g_q16l + off) = pack2h(__float2half(r0 - __half2float(h0)),
                                                __float2half(r1 - __half2float(h1)));
        } else if (n < 1280) {
            int i = (n & 63) >> 1;
            float c = fcos[t * 32 + i], s = fsin[t * 32 + i];
            *(uint32_t*)(g_k16 + (size_t)r * 320 + (n - 960)) =
                pack2h(__float2half(a0 * c - a1 * s), __float2half(a0 * s + a1 * c));
        } else {
            *(uint32_t*)(g_v16 + (size_t)r * 320 + (n - 1280)) =
                pack2h(__float2half(a0), __float2half(a1));
        }
    };

#pragma unroll
    for (int mt = 0; mt < 2; mt++) {
#pragma unroll
        for (int nt = 0; nt < 4; nt++) {
            const int m = m0 + wm * 32 + mt * 16 + (lane >> 2);
            const int n = n0 + wn * 32 + nt * 8 + (lane & 3) * 2;
            store_pair(m,     n, acc[mt][nt][0], acc[mt][nt][1]);
            store_pair(m + 8, n, acc[mt][nt][2], acc[mt][nt][3]);
        }
    }
}

// ---------------- convert / transpose helpers ---------------------------------
__global__ void convert_f16_kernel(const float* __restrict__ src,
                                   __half* __restrict__ dst, int n) {
    int idx = blockIdx.x * blockDim.x + threadIdx.x;
    if (idx >= n) return;
    dst[idx] = __float2half(src[idx]);
}

// W[K][N] -> Wt[n*K + k] fp16
__global__ void transpose_f16_kernel(const float* __restrict__ W,
                                     __half* __restrict__ dst, int K, int N) {
    __shared__ float tile[32][33];
    int k0 = blockIdx.y * 32, n0 = blockIdx.x * 32;
    int tx = threadIdx.x, ty = threadIdx.y;
#pragma unroll
    for (int i = 0; i < 4; i++)
        tile[ty + i * 8][tx] = W[(size_t)(k0 + ty + i * 8) * N + n0 + tx];
    __syncthreads();
#pragma unroll
    for (int i = 0; i < 4; i++) {
        int n = n0 + ty + i * 8;
        dst[(size_t)n * K + k0 + tx] = __float2half(tile[tx][ty + i * 8]);
    }
}

// ---------------- Flash attention on mma.sync fp16 (causal, GQA) --------------
// Q fp16 hi+lo (2-pass QK), K/V/P single fp16 (1-pass PV).
// block: 128 threads (4 warps), 64 q rows; qt reversed for wave balance.
#define AT_PITCH 144
#define AT_QL 9216
#define AT_VH 9216
#define AT_STAGE 18432
#define ATTN_SMEM (2 * AT_STAGE)    // 36864

__global__ void __launch_bounds__(128)
attn_mma_kernel(const __half* __restrict__ Qhi, const __half* __restrict__ Qlo,
                const __half* __restrict__ Khi, const __half* __restrict__ Vhi,
                __half* __restrict__ O16)
{
    extern __shared__ __align__(128) char smem[];
    const uint32_t sbase = smem_to_u32(smem);
    const int tid = threadIdx.x, wid = tid >> 5, lane = tid & 31;
    const int qt = gridDim.x - 1 - blockIdx.x;
    const int h = blockIdx.y, b = blockIdx.z;
    const int kvh = h / GQA;

    // ---- stage Q through smem (stage 0 area), extract fragments
    {
        int r = tid >> 1, half = tid & 1;
        size_t gq = ((size_t)(b * SEQ + qt * 64 + r) * NH + h) * HD + half * 32;
        const uint4* ph = (const uint4*)(Qhi + gq);
        const uint4* pl = (const uint4*)(Qlo + gq);
        char* dsth = smem + r * AT_PITCH + half * 64;
        char* dstl = smem + AT_QL + r * AT_PITCH + half * 64;
#pragma unroll
        for (int c = 0; c < 4; c++) { ((uint4*)dsth)[c] = ph[c]; ((uint4*)dstl)[c] = pl[c]; }
    }
    __syncthreads();
    uint32_t qh[4][4], ql[4][4];
    {
        const int a_r = lane & 15, a_cb = (lane >> 4) * 16;
#pragma unroll
        for (int kk = 0; kk < 4; kk++) {
            uint32_t addr = sbase + (wid * 16 + a_r) * AT_PITCH + kk * 32 + a_cb;
            ldsm_x4(qh[kk], addr);
            ldsm_x4(ql[kk], addr + AT_QL);
        }
    }
    __syncthreads();

    auto load_kv = [&](int kt) {
        uint32_t st = sbase + (kt & 1) * AT_STAGE;
        int jr = tid >> 1, cs = (tid & 1) * 4;
        size_t g = ((size_t)(b * SEQ + kt * 64 + jr) * NKV + kvh) * HD + cs * 8;
        uint32_t so = st + jr * AT_PITCH + cs * 16;
#pragma unroll
        for (int c = 0; c < 4; c++) {
            cp_async16(so + c * 16,          Khi + g + c * 8);
            cp_async16(so + AT_VH + c * 16,  Vhi + g + c * 8);
        }
    };

    float O[8][4];
#pragma unroll
    for (int i = 0; i < 8; i++)
#pragma unroll
        for (int j = 0; j < 4; j++) O[i][j] = 0.f;
    float m0 = -CUDART_INF_F, m1 = -CUDART_INF_F;
    float l0 = 0.f, l1 = 0.f;

    load_kv(0); CP_COMMIT();
    if (qt >= 1) load_kv(1);
    CP_COMMIT();

    const int b_rin = lane & 7;
    const int b_mat = lane >> 3;
    const int b_nof = (b_mat >> 1) * 8 + b_rin;
    const int b_kb  = (b_mat & 1) * 16;
    const int v_r   = lane & 15;
    const int v_cb  = (lane >> 4) * 16;
    const int r0loc = wid * 16 + (lane >> 2);

    for (int kt = 0; kt <= qt; kt++) {
        CP_WAIT1();
        __syncthreads();
        const uint32_t st = sbase + (kt & 1) * AT_STAGE;

        // ---- S = Q K^T (2-pass fp16: Qh*K + Ql*K)
        float S[8][4];
#pragma unroll
        for (int i = 0; i < 8; i++)
#pragma unroll
            for (int j = 0; j < 4; j++) S[i][j] = 0.f;

#pragma unroll
        for (int kk = 0; kk < 4; kk++) {
            uint32_t kb[16];
#pragma unroll
            for (int g2 = 0; g2 < 4; g2++) {
                uint32_t addr = st + (g2 * 16 + b_nof) * AT_PITCH + kk * 32 + b_kb;
                ldsm_x4(&kb[g2 * 4], addr);
            }
#pragma unroll
            for (int nt = 0; nt < 8; nt++) {
                mma_f16(S[nt], qh[kk], &kb[nt * 2]);
                mma_f16(S[nt], ql[kk], &kb[nt * 2]);
            }
        }

        // ---- causal mask (diag tile only)
        if (kt == qt) {
#pragma unroll
            for (int nt = 0; nt < 8; nt++) {
                int col = nt * 8 + (lane & 3) * 2;
                if (col     > r0loc)     S[nt][0] = -CUDART_INF_F;
                if (col + 1 > r0loc)     S[nt][1] = -CUDART_INF_F;
                if (col     > r0loc + 8) S[nt][2] = -CUDART_INF_F;
                if (col + 1 > r0loc + 8) S[nt][3] = -CUDART_INF_F;
            }
        }

        // ---- online softmax
        float t0 = -CUDART_INF_F, t1 = -CUDART_INF_F;
#pragma unroll
        for (int nt = 0; nt < 8; nt++) {
            t0 = fmaxf(t0, fmaxf(S[nt][0], S[nt][1]));
            t1 = fmaxf(t1, fmaxf(S[nt][2], S[nt][3]));
        }
        t0 = fmaxf(t0, __shfl_xor_sync(0xffffffffu, t0, 1));
        t0 = fmaxf(t0, __shfl_xor_sync(0xffffffffu, t0, 2));
        t1 = fmaxf(t1, __shfl_xor_sync(0xffffffffu, t1, 1));
        t1 = fmaxf(t1, __shfl_xor_sync(0xffffffffu, t1, 2));
        float mn0 = fmaxf(m0, t0), mn1 = fmaxf(m1, t1);
        float c0 = __expf(m0 - mn0), c1 = __expf(m1 - mn1);
        m0 = mn0; m1 = mn1;

        // ---- P = exp(S - m), single fp16 (l accumulated in fp32)
        uint32_t pk[4][4];
        float la0 = 0.f, la1 = 0.f;
#pragma unroll
        for (int t = 0; t < 4; t++) {
            float p[8];
            p[0] = __expf(S[2*t][0] - mn0);   p[1] = __expf(S[2*t][1] - mn0);
            p[2] = __expf(S[2*t][2] - mn1);   p[3] = __expf(S[2*t][3] - mn1);
            p[4] = __expf(S[2*t+1][0] - mn0); p[5] = __expf(S[2*t+1][1] - mn0);
            p[6] = __expf(S[2*t+1][2] - mn1); p[7] = __expf(S[2*t+1][3] - mn1);
            la0 += p[0] + p[1] + p[4] + p[5];
            la1 += p[2] + p[3] + p[6] + p[7];
            pk[t][0] = pack2h(__float2half(p[0]), __float2half(p[1]));
            pk[t][1] = pack2h(__float2half(p[2]), __float2half(p[3]));
            pk[t][2] = pack2h(__float2half(p[4]), __float2half(p[5]));
            pk[t][3] = pack2h(__float2half(p[6]), __float2half(p[7]));
        }
        l0 = l0 * c0 + la0;
        l1 = l1 * c1 + la1;

#pragma unroll
        for (int dt = 0; dt < 8; dt++) {
            O[dt][0] *= c0; O[dt][1] *= c0;
            O[dt][2] *= c1; O[dt][3] *= c1;
        }

        // ---- O += P V (1-pass fp16)
#pragma unroll
        for (int t = 0; t < 4; t++) {
            uint32_t vb[16];
#pragma unroll
            for (int db = 0; db < 4; db++) {
                uint32_t addr = st + AT_VH + (t * 16 + v_r) * AT_PITCH + db * 32 + v_cb;
                ldsm_x4_trans(&vb[db * 4], addr);
            }
#pragma unroll
            for (int dt = 0; dt < 8; dt++)
                mma_f16(O[dt], pk[t], &vb[dt * 2]);
        }

        __syncthreads();
        if (kt + 2 <= qt) load_kv(kt + 2);
        CP_COMMIT();
    }

    // ---- finalize: normalize, store fp16
    l0 += __shfl_xor_sync(0xffffffffu, l0, 1);
    l0 += __shfl_xor_sync(0xffffffffu, l0, 2);
    l1 += __shfl_xor_sync(0xffffffffu, l1, 1);
    l1 += __shfl_xor_sync(0xffffffffu, l1, 2);
    float inv0 = 1.f / l0, inv1 = 1.f / l1;

    const int row0 = qt * 64 + r0loc;
#pragma unroll
    for (int dt = 0; dt < 8; dt++) {
        int d = dt * 8 + (lane & 3) * 2;
        size_t o0 = ((size_t)(b * SEQ + row0) * NH + h) * HD + d;
        size_t o1 = o0 + (size_t)8 * NH * HD;
        *(uint32_t*)(O16 + o0) = pack2h(__float2half(O[dt][0] * inv0),
                                        __float2half(O[dt][1] * inv0));
        *(uint32_t*)(O16 + o1) = pack2h(__float2half(O[dt][2] * inv1),
                                        __float2half(O[dt][3] * inv1));
    }
}

// ---------------- launcher ----------------------------------------------------
extern "C" void kernel_launch(void* const* d_in, const int* in_sizes, int n_in,
                              void* d_out, int out_size) {
    const float* x    = (const float*)d_in[0];
    const float* fcos = (const float*)d_in[1];
    const float* fsin = (const float*)d_in[2];
    const float* wq   = (const float*)d_in[3];
    const float* wk   = (const float*)d_in[4];
    const float* wv   = (const float*)d_in[5];
    const float* wo   = (const float*)d_in[6];
    float* out = (float*)d_out;

    __half *x16, *o16, *q16h, *q16l, *k16, *v16, *wqkv, *wot;
    cudaGetSymbolAddress((void**)&x16, g_x16);
    cudaGetSymbolAddress((void**)&o16, g_o16);
    cudaGetSymbolAddress((void**)&q16h, g_q16h);
    cudaGetSymbolAddress((void**)&q16l, g_q16l);
    cudaGetSymbolAddress((void**)&k16, g_k16);
    cudaGetSymbolAddress((void**)&v16, g_v16);
    cudaGetSymbolAddress((void**)&wqkv, g_wqkv);
    cudaGetSymbolAddress((void**)&wot, g_wot);

    cudaFuncSetAttribute(gemm_out_kernel,
                         cudaFuncAttributeMaxDynamicSharedMemorySize, GEMM_SMEM);
    cudaFuncSetAttribute(gemm_qkv_kernel,
                         cudaFuncAttributeMaxDynamicSharedMemorySize, GEMM_SMEM);
    cudaFuncSetAttribute(attn_mma_kernel,
                         cudaFuncAttributeMaxDynamicSharedMemorySize, ATTN_SMEM);

    // input -> fp16; weight transposes (concatenated rows for QKV)
    {
        int n = MTOK * DIM;
        convert_f16_kernel<<<(n + 255) / 256, 256>>>(x, x16, n);
    }
    transpose_f16_kernel<<<dim3(960 / 32, 960 / 32), dim3(32, 8)>>>(wq, wqkv, DIM, 960);
    transpose_f16_kernel<<<dim3(320 / 32, 960 / 32), dim3(32, 8)>>>(
        wk, wqkv + (size_t)960 * 960, DIM, 320);
    transpose_f16_kernel<<<dim3(320 / 32, 960 / 32), dim3(32, 8)>>>(
        wv, wqkv + (size_t)1280 * 960, DIM, 320);
    transpose_f16_kernel<<<dim3(960 / 32, 960 / 32), dim3(32, 8)>>>(wo, wot, 960, 960);

    // fused QKV projection + RoPE epilogue (fp16 1-pass GEMM)
    gemm_qkv_kernel<<<dim3(QKV_N / BN, MTOK / BM), 256, GEMM_SMEM>>>(
        x16, wqkv, fcos, fsin);

    // flash attention (fp16 tensor cores)
    attn_mma_kernel<<<dim3(SEQ / 64, NH, BATCH), 128, ATTN_SMEM>>>(
        q16h, q16l, k16, v16, o16);

    // output projection (fp16 1-pass GEMM)
    gemm_out_kernel<<<dim3(960 / BN, MTOK / BM), 256, GEMM_SMEM>>>(
        o16, wot, out, MTOK, 960, 960);
}

// round 14
// speedup vs baseline: 3.5639x; 1.1039x over previous
#include <cuda_runtime.h>
#include <cuda_bf16.h>
#include <cuda_fp16.h>
#include <math_constants.h>
#include <cstdint>

// Problem constants
#define BATCH 4
#define SEQ 2048
#define DIM 960
#define NH 15
#define NKV 5
#define HD 64
#define GQA 3
#define MTOK (BATCH*SEQ)   // 8192
#define QKV_N 1600         // 960 q + 320 k + 320 v

// ---------------- scratch (device globals; no allocations) ----------------
__device__ __half g_x16[(size_t)MTOK * DIM];
__device__ __half g_o16[(size_t)MTOK * DIM];          // attention out (fp16)
__device__ __half g_q16[(size_t)MTOK * NH * HD];
__device__ __half g_k16[(size_t)MTOK * NKV * HD];
__device__ __half g_v16[(size_t)MTOK * NKV * HD];
__device__ __half g_wqkv[(size_t)QKV_N * 960];        // transposed fp16
__device__ __half g_wot[(size_t)960 * 960];           // transposed fp16

// ---------------- small PTX helpers ------------------------------------------
__device__ __forceinline__ uint32_t smem_to_u32(const void* p) {
    uint32_t a;
    asm("{ .reg .u64 t; cvta.to.shared.u64 t, %1; cvt.u32.u64 %0, t; }" : "=r"(a) : "l"(p));
    return a;
}
__device__ __forceinline__ void cp_async16(uint32_t saddr, const void* gptr) {
    asm volatile("cp.async.cg.shared.global [%0], [%1], 16;" :: "r"(saddr), "l"(gptr));
}
#define CP_COMMIT() asm volatile("cp.async.commit_group;" ::: "memory")
#define CP_WAIT1()  asm volatile("cp.async.wait_group 1;" ::: "memory")

__device__ __forceinline__ void ldsm_x4(uint32_t* r, uint32_t addr) {
    asm volatile("ldmatrix.sync.aligned.m8n8.x4.shared.b16 {%0,%1,%2,%3}, [%4];"
                 : "=r"(r[0]), "=r"(r[1]), "=r"(r[2]), "=r"(r[3]) : "r"(addr));
}
__device__ __forceinline__ void ldsm_x4_trans(uint32_t* r, uint32_t addr) {
    asm volatile("ldmatrix.sync.aligned.m8n8.x4.trans.shared.b16 {%0,%1,%2,%3}, [%4];"
                 : "=r"(r[0]), "=r"(r[1]), "=r"(r[2]), "=r"(r[3]) : "r"(addr));
}
__device__ __forceinline__ void mma_f16(float* d, const uint32_t* a, const uint32_t* b) {
    asm volatile(
        "mma.sync.aligned.m16n8k16.row.col.f32.f16.f16.f32 "
        "{%0,%1,%2,%3}, {%4,%5,%6,%7}, {%8,%9}, {%0,%1,%2,%3};"
        : "+f"(d[0]), "+f"(d[1]), "+f"(d[2]), "+f"(d[3])
        : "r"(a[0]), "r"(a[1]), "r"(a[2]), "r"(a[3]), "r"(b[0]), "r"(b[1]));
}
__device__ __forceinline__ uint32_t pack2h(__half a, __half b) {
    __half2 t = __halves2half2(a, b);
    return *(uint32_t*)&t;
}

// ---------------- plain fp16 GEMM core macros ---------------------------------
#define BM 128
#define BN 64
#define BK 32
#define NSTAGE 3
#define A_PITCH 80
#define SB_OFF (128 * A_PITCH)
#define STAGE_BYTES (SB_OFF + 64 * A_PITCH)  // 15360
#define GEMM_SMEM (NSTAGE * STAGE_BYTES)     // 46080

#define GEMM_MAINLOOP(A16, B16, K)                                                   \
    const uint32_t sbase = smem_to_u32(smem);                                        \
    const int tid  = threadIdx.x;                                                    \
    const int wid  = tid >> 5;                                                       \
    const int lane = tid & 31;                                                       \
    const int m0 = blockIdx.y * BM;                                                  \
    const int n0 = blockIdx.x * BN;                                                  \
    const int wm = wid >> 1;                                                         \
    const int wn = wid & 1;                                                          \
    const int nchunk = (K) / BK;                                                     \
    const int arow = tid >> 1;                                                       \
    const int acol = (tid & 1) * 2;                                                  \
    const int brow = tid >> 2;                                                       \
    const int bcol = tid & 3;                                                        \
    auto load_stage = [&](int ci, int s) {                                           \
        const uint32_t st = sbase + s * STAGE_BYTES;                                 \
        const int k0 = ci * BK;                                                      \
        {                                                                            \
            const size_t go = (size_t)(m0 + arow) * (K) + k0 + acol * 8;             \
            const uint32_t so = st + arow * A_PITCH + acol * 16;                     \
            cp_async16(so,      (A16) + go);                                         \
            cp_async16(so + 16, (A16) + go + 8);                                     \
        }                                                                            \
        {                                                                            \
            const size_t go = (size_t)(n0 + brow) * (K) + k0 + bcol * 8;             \
            const uint32_t so = st + SB_OFF + brow * A_PITCH + bcol * 16;            \
            cp_async16(so, (B16) + go);                                              \
        }                                                                            \
    };                                                                               \
    float acc[2][4][4];                                                              \
    _Pragma("unroll")                                                                \
    for (int i = 0; i < 2; i++)                                                      \
        _Pragma("unroll")                                                            \
        for (int j = 0; j < 4; j++)                                                  \
            _Pragma("unroll")                                                        \
            for (int v = 0; v < 4; v++) acc[i][j][v] = 0.f;                          \
    load_stage(0, 0); CP_COMMIT();                                                   \
    load_stage(1, 1); CP_COMMIT();                                                   \
    const int a_r   = lane & 15;                                                     \
    const int a_cb  = (lane >> 4) * 16;                                              \
    const int b_mat = lane >> 3;                                                     \
    const int b_rin = lane & 7;                                                      \
    const int b_nof = (b_mat >> 1) * 8 + b_rin;                                      \
    const int b_kb  = (b_mat & 1) * 16;                                              \
    for (int i = 0; i < nchunk; i++) {                                               \
        CP_WAIT1();                                                                  \
        __syncthreads();                                                             \
        if (i + 2 < nchunk) load_stage(i + 2, (i + 2) % NSTAGE);                     \
        CP_COMMIT();                                                                 \
        const uint32_t st = sbase + (i % NSTAGE) * STAGE_BYTES;                      \
        _Pragma("unroll")                                                            \
        for (int kk = 0; kk < 2; kk++) {                                             \
            const int kbyte = kk * 32;                                               \
            uint32_t ah[2][4], bh[8];                                                \
            _Pragma("unroll")                                                        \
            for (int mt = 0; mt < 2; mt++) {                                         \
                uint32_t addr = st + (wm * 32 + mt * 16 + a_r) * A_PITCH + kbyte + a_cb; \
                ldsm_x4(ah[mt], addr);                                               \
            }                                                                        \
            _Pragma("unroll")                                                        \
            for (int hh = 0; hh < 2; hh++) {                                         \
                uint32_t addr = st + SB_OFF + (wn * 32 + hh * 16 + b_nof) * A_PITCH + kbyte + b_kb; \
                ldsm_x4(&bh[hh * 4], addr);                                          \
            }                                                                        \
            _Pragma("unroll")                                                        \
            for (int mt = 0; mt < 2; mt++)                                           \
                _Pragma("unroll")                                                    \
                for (int nt = 0; nt < 4; nt++)                                       \
                    mma_f16(acc[mt][nt], ah[mt], &bh[nt * 2]);                       \
        }                                                                            \
        __syncthreads();                                                             \
    }

// ---------------- output-proj GEMM (fp32 epilogue) ----------------------------
__global__ void __launch_bounds__(256, 2)
gemm_out_kernel(const __half* __restrict__ A16,
                const __half* __restrict__ B16,
                float* __restrict__ C, int M, int N, int K)
{
    extern __shared__ __align__(128) char smem[];
    GEMM_MAINLOOP(A16, B16, K)
#pragma unroll
    for (int mt = 0; mt < 2; mt++) {
#pragma unroll
        for (int nt = 0; nt < 4; nt++) {
            const int m = m0 + wm * 32 + mt * 16 + (lane >> 2);
            const int n = n0 + wn * 32 + nt * 8 + (lane & 3) * 2;
            *(float2*)&C[(size_t)m * N + n]       = make_float2(acc[mt][nt][0], acc[mt][nt][1]);
            *(float2*)&C[(size_t)(m + 8) * N + n] = make_float2(acc[mt][nt][2], acc[mt][nt][3]);
        }
    }
}

// ---------------- fused QKV GEMM with RoPE epilogue ---------------------------
// N=1600: cols [0,960) -> q (rope, *0.125), [960,1280) -> k (rope), [1280,1600) -> v.
__global__ void __launch_bounds__(256, 2)
gemm_qkv_kernel(const __half* __restrict__ A16,
                const __half* __restrict__ B16,
                const float* __restrict__ fcos, const float* __restrict__ fsin)
{
    extern __shared__ __align__(128) char smem[];
    GEMM_MAINLOOP(A16, B16, DIM)

    auto store_pair = [&](int r, int n, float a0, float a1) {
        int t = r & (SEQ - 1);
        if (n < 960) {
            int i = (n & 63) >> 1;
            float c = fcos[t * 32 + i], s = fsin[t * 32 + i];
            *(uint32_t*)(g_q16 + (size_t)r * 960 + n) =
                pack2h(__float2half((a0 * c - a1 * s) * 0.125f),
                       __float2half((a0 * s + a1 * c) * 0.125f));
        } else if (n < 1280) {
            int i = (n & 63) >> 1;
            float c = fcos[t * 32 + i], s = fsin[t * 32 + i];
            *(uint32_t*)(g_k16 + (size_t)r * 320 + (n - 960)) =
                pack2h(__float2half(a0 * c - a1 * s), __float2half(a0 * s + a1 * c));
        } else {
            *(uint32_t*)(g_v16 + (size_t)r * 320 + (n - 1280)) =
                pack2h(__float2half(a0), __float2half(a1));
        }
    };

#pragma unroll
    for (int mt = 0; mt < 2; mt++) {
#pragma unroll
        for (int nt = 0; nt < 4; nt++) {
            const int m = m0 + wm * 32 + mt * 16 + (lane >> 2);
            const int n = n0 + wn * 32 + nt * 8 + (lane & 3) * 2;
            store_pair(m,     n, acc[mt][nt][0], acc[mt][nt][1]);
            store_pair(m + 8, n, acc[mt][nt][2], acc[mt][nt][3]);
        }
    }
}

// ---------------- convert / combined transpose helpers ------------------------
__global__ void convert_f16_kernel(const float* __restrict__ src,
                                   __half* __restrict__ dst, int n) {
    int idx = blockIdx.x * blockDim.x + threadIdx.x;
    if (idx >= n) return;
    dst[idx] = __float2half(src[idx]);
}

// All four weight transposes in one launch. n-tile index over concatenated
// columns [wq 960 | wk 320 | wv 320 | wo 960] = 2560; K=960 for all.
__global__ void transpose_all_f16_kernel(const float* __restrict__ wq,
                                         const float* __restrict__ wk,
                                         const float* __restrict__ wv,
                                         const float* __restrict__ wo) {
    __shared__ float tile[32][33];
    const int ng = blockIdx.x * 32;       // global column base 0..2559
    const int k0 = blockIdx.y * 32;
    const float* src; __half* dst; int N; int nloc;
    if (ng < 960)       { src = wq; dst = g_wqkv;                     N = 960; nloc = ng; }
    else if (ng < 1280) { src = wk; dst = g_wqkv + (size_t)960 * 960; N = 320; nloc = ng - 960; }
    else if (ng < 1600) { src = wv; dst = g_wqkv + (size_t)1280 * 960; N = 320; nloc = ng - 1280; }
    else                { src = wo; dst = g_wot;                      N = 960; nloc = ng - 1600; }

    int tx = threadIdx.x, ty = threadIdx.y;  // (32, 8)
#pragma unroll
    for (int i = 0; i < 4; i++)
        tile[ty + i * 8][tx] = src[(size_t)(k0 + ty + i * 8) * N + nloc + tx];
    __syncthreads();
#pragma unroll
    for (int i = 0; i < 4; i++) {
        int n = nloc + ty + i * 8;
        dst[(size_t)n * 960 + k0 + tx] = __float2half(tile[tx][ty + i * 8]);
    }
}

// ---------------- Flash attention on mma.sync fp16 (causal, GQA) --------------
// Q/K/V/P all single fp16 (1-pass QK, 1-pass PV), fp32 accum + fp32 l.
// block: 128 threads (4 warps), 64 q rows; qt reversed for wave balance.
#define AT_PITCH 144
#define AT_VH 9216
#define AT_STAGE 18432
#define ATTN_SMEM (2 * AT_STAGE)    // 36864

__global__ void __launch_bounds__(128)
attn_mma_kernel(const __half* __restrict__ Q16,
                const __half* __restrict__ Khi, const __half* __restrict__ Vhi,
                __half* __restrict__ O16)
{
    extern __shared__ __align__(128) char smem[];
    const uint32_t sbase = smem_to_u32(smem);
    const int tid = threadIdx.x, wid = tid >> 5, lane = tid & 31;
    const int qt = gridDim.x - 1 - blockIdx.x;
    const int h = blockIdx.y, b = blockIdx.z;
    const int kvh = h / GQA;

    // ---- stage Q through smem (stage 0 area), extract fragments
    {
        int r = tid >> 1, half = tid & 1;
        size_t gq = ((size_t)(b * SEQ + qt * 64 + r) * NH + h) * HD + half * 32;
        const uint4* ph = (const uint4*)(Q16 + gq);
        char* dsth = smem + r * AT_PITCH + half * 64;
#pragma unroll
        for (int c = 0; c < 4; c++) ((uint4*)dsth)[c] = ph[c];
    }
    __syncthreads();
    uint32_t qh[4][4];
    {
        const int a_r = lane & 15, a_cb = (lane >> 4) * 16;
#pragma unroll
        for (int kk = 0; kk < 4; kk++) {
            uint32_t addr = sbase + (wid * 16 + a_r) * AT_PITCH + kk * 32 + a_cb;
            ldsm_x4(qh[kk], addr);
        }
    }
    __syncthreads();

    auto load_kv = [&](int kt) {
        uint32_t st = sbase + (kt & 1) * AT_STAGE;
        int jr = tid >> 1, cs = (tid & 1) * 4;
        size_t g = ((size_t)(b * SEQ + kt * 64 + jr) * NKV + kvh) * HD + cs * 8;
        uint32_t so = st + jr * AT_PITCH + cs * 16;
#pragma unroll
        for (int c = 0; c < 4; c++) {
            cp_async16(so + c * 16,          Khi + g + c * 8);
            cp_async16(so + AT_VH + c * 16,  Vhi + g + c * 8);
        }
    };

    float O[8][4];
#pragma unroll
    for (int i = 0; i < 8; i++)
#pragma unroll
        for (int j = 0; j < 4; j++) O[i][j] = 0.f;
    float m0 = -CUDART_INF_F, m1 = -CUDART_INF_F;
    float l0 = 0.f, l1 = 0.f;

    load_kv(0); CP_COMMIT();
    if (qt >= 1) load_kv(1);
    CP_COMMIT();

    const int b_rin = lane & 7;
    const int b_mat = lane >> 3;
    const int b_nof = (b_mat >> 1) * 8 + b_rin;
    const int b_kb  = (b_mat & 1) * 16;
    const int v_r   = lane & 15;
    const int v_cb  = (lane >> 4) * 16;
    const int r0loc = wid * 16 + (lane >> 2);

    for (int kt = 0; kt <= qt; kt++) {
        CP_WAIT1();
        __syncthreads();
        const uint32_t st = sbase + (kt & 1) * AT_STAGE;

        // ---- S = Q K^T (1-pass fp16)
        float S[8][4];
#pragma unroll
        for (int i = 0; i < 8; i++)
#pragma unroll
            for (int j = 0; j < 4; j++) S[i][j] = 0.f;

#pragma unroll
        for (int kk = 0; kk < 4; kk++) {
            uint32_t kb[16];
#pragma unroll
            for (int g2 = 0; g2 < 4; g2++) {
                uint32_t addr = st + (g2 * 16 + b_nof) * AT_PITCH + kk * 32 + b_kb;
                ldsm_x4(&kb[g2 * 4], addr);
            }
#pragma unroll
            for (int nt = 0; nt < 8; nt++)
                mma_f16(S[nt], qh[kk], &kb[nt * 2]);
        }

        // ---- causal mask (diag tile only)
        if (kt == qt) {
#pragma unroll
            for (int nt = 0; nt < 8; nt++) {
                int col = nt * 8 + (lane & 3) * 2;
                if (col     > r0loc)     S[nt][0] = -CUDART_INF_F;
                if (col + 1 > r0loc)     S[nt][1] = -CUDART_INF_F;
                if (col     > r0loc + 8) S[nt][2] = -CUDART_INF_F;
                if (col + 1 > r0loc + 8) S[nt][3] = -CUDART_INF_F;
            }
        }

        // ---- online softmax
        float t0 = -CUDART_INF_F, t1 = -CUDART_INF_F;
#pragma unroll
        for (int nt = 0; nt < 8; nt++) {
            t0 = fmaxf(t0, fmaxf(S[nt][0], S[nt][1]));
            t1 = fmaxf(t1, fmaxf(S[nt][2], S[nt][3]));
        }
        t0 = fmaxf(t0, __shfl_xor_sync(0xffffffffu, t0, 1));
        t0 = fmaxf(t0, __shfl_xor_sync(0xffffffffu, t0, 2));
        t1 = fmaxf(t1, __shfl_xor_sync(0xffffffffu, t1, 1));
        t1 = fmaxf(t1, __shfl_xor_sync(0xffffffffu, t1, 2));
        float mn0 = fmaxf(m0, t0), mn1 = fmaxf(m1, t1);
        float c0 = __expf(m0 - mn0), c1 = __expf(m1 - mn1);
        m0 = mn0; m1 = mn1;

        // ---- P = exp(S - m), single fp16 (l accumulated in fp32)
        uint32_t pk[4][4];
        float la0 = 0.f, la1 = 0.f;
#pragma unroll
        for (int t = 0; t < 4; t++) {
            float p[8];
            p[0] = __expf(S[2*t][0] - mn0);   p[1] = __expf(S[2*t][1] - mn0);
            p[2] = __expf(S[2*t][2] - mn1);   p[3] = __expf(S[2*t][3] - mn1);
            p[4] = __expf(S[2*t+1][0] - mn0); p[5] = __expf(S[2*t+1][1] - mn0);
            p[6] = __expf(S[2*t+1][2] - mn1); p[7] = __expf(S[2*t+1][3] - mn1);
            la0 += p[0] + p[1] + p[4] + p[5];
            la1 += p[2] + p[3] + p[6] + p[7];
            pk[t][0] = pack2h(__float2half(p[0]), __float2half(p[1]));
            pk[t][1] = pack2h(__float2half(p[2]), __float2half(p[3]));
            pk[t][2] = pack2h(__float2half(p[4]), __float2half(p[5]));
            pk[t][3] = pack2h(__float2half(p[6]), __float2half(p[7]));
        }
        l0 = l0 * c0 + la0;
        l1 = l1 * c1 + la1;

#pragma unroll
        for (int dt = 0; dt < 8; dt++) {
            O[dt][0] *= c0; O[dt][1] *= c0;
            O[dt][2] *= c1; O[dt][3] *= c1;
        }

        // ---- O += P V (1-pass fp16)
#pragma unroll
        for (int t = 0; t < 4; t++) {
            uint32_t vb[16];
#pragma unroll
            for (int db = 0; db < 4; db++) {
                uint32_t addr = st + AT_VH + (t * 16 + v_r) * AT_PITCH + db * 32 + v_cb;
                ldsm_x4_trans(&vb[db * 4], addr);
            }
#pragma unroll
            for (int dt = 0; dt < 8; dt++)
                mma_f16(O[dt], pk[t], &vb[dt * 2]);
        }

        __syncthreads();
        if (kt + 2 <= qt) load_kv(kt + 2);
        CP_COMMIT();
    }

    // ---- finalize: normalize, store fp16
    l0 += __shfl_xor_sync(0xffffffffu, l0, 1);
    l0 += __shfl_xor_sync(0xffffffffu, l0, 2);
    l1 += __shfl_xor_sync(0xffffffffu, l1, 1);
    l1 += __shfl_xor_sync(0xffffffffu, l1, 2);
    float inv0 = 1.f / l0, inv1 = 1.f / l1;

    const int row0 = qt * 64 + r0loc;
#pragma unroll
    for (int dt = 0; dt < 8; dt++) {
        int d = dt * 8 + (lane & 3) * 2;
        size_t o0 = ((size_t)(b * SEQ + row0) * NH + h) * HD + d;
        size_t o1 = o0 + (size_t)8 * NH * HD;
        *(uint32_t*)(O16 + o0) = pack2h(__float2half(O[dt][0] * inv0),
                                        __float2half(O[dt][1] * inv0));
        *(uint32_t*)(O16 + o1) = pack2h(__float2half(O[dt][2] * inv1),
                                        __float2half(O[dt][3] * inv1));
    }
}

// ---------------- launcher ----------------------------------------------------
extern "C" void kernel_launch(void* const* d_in, const int* in_sizes, int n_in,
                              void* d_out, int out_size) {
    const float* x    = (const float*)d_in[0];
    const float* fcos = (const float*)d_in[1];
    const float* fsin = (const float*)d_in[2];
    const float* wq   = (const float*)d_in[3];
    const float* wk   = (const float*)d_in[4];
    const float* wv   = (const float*)d_in[5];
    const float* wo   = (const float*)d_in[6];
    float* out = (float*)d_out;

    __half *x16, *o16, *q16, *k16, *v16, *wqkv, *wot;
    cudaGetSymbolAddress((void**)&x16, g_x16);
    cudaGetSymbolAddress((void**)&o16, g_o16);
    cudaGetSymbolAddress((void**)&q16, g_q16);
    cudaGetSymbolAddress((void**)&k16, g_k16);
    cudaGetSymbolAddress((void**)&v16, g_v16);
    cudaGetSymbolAddress((void**)&wqkv, g_wqkv);
    cudaGetSymbolAddress((void**)&wot, g_wot);

    cudaFuncSetAttribute(gemm_out_kernel,
                         cudaFuncAttributeMaxDynamicSharedMemorySize, GEMM_SMEM);
    cudaFuncSetAttribute(gemm_qkv_kernel,
                         cudaFuncAttributeMaxDynamicSharedMemorySize, GEMM_SMEM);
    cudaFuncSetAttribute(attn_mma_kernel,
                         cudaFuncAttributeMaxDynamicSharedMemorySize, ATTN_SMEM);

    // input -> fp16; all weight transposes in one launch
    {
        int n = MTOK * DIM;
        convert_f16_kernel<<<(n + 255) / 256, 256>>>(x, x16, n);
    }
    transpose_all_f16_kernel<<<dim3(2560 / 32, 960 / 32), dim3(32, 8)>>>(wq, wk, wv, wo);

    // fused QKV projection + RoPE epilogue (fp16 1-pass GEMM)
    gemm_qkv_kernel<<<dim3(QKV_N / BN, MTOK / BM), 256, GEMM_SMEM>>>(
        x16, wqkv, fcos, fsin);

    // flash attention (fp16 tensor cores, 1-pass QK / 1-pass PV)
    attn_mma_kernel<<<dim3(SEQ / 64, NH, BATCH), 128, ATTN_SMEM>>>(
        q16, k16, v16, o16);

    // output projection (fp16 1-pass GEMM)
    gemm_out_kernel<<<dim3(960 / BN, MTOK / BM), 256, GEMM_SMEM>>>(
        o16, wot, out, MTOK, 960, 960);
}

// round 15
// speedup vs baseline: 3.5816x; 1.0050x over previous
#include <cuda_runtime.h>
#include <cuda_bf16.h>
#include <cuda_fp16.h>
#include <math_constants.h>
#include <cstdint>

// Problem constants
#define BATCH 4
#define SEQ 2048
#define DIM 960
#define NH 15
#define NKV 5
#define HD 64
#define GQA 3
#define MTOK (BATCH*SEQ)   // 8192
#define QKV_N 1600         // 960 q + 320 k + 320 v

// ---------------- scratch (device globals; no allocations) ----------------
__device__ __half g_x16[(size_t)MTOK * DIM];
__device__ __half g_o16[(size_t)MTOK * DIM];          // attention out (fp16)
__device__ __half g_q16[(size_t)MTOK * NH * HD];
__device__ __half g_k16[(size_t)MTOK * NKV * HD];
__device__ __half g_v16[(size_t)MTOK * NKV * HD];
__device__ __half g_wqkv[(size_t)QKV_N * 960];        // transposed fp16
__device__ __half g_wot[(size_t)960 * 960];           // transposed fp16

// ---------------- small PTX helpers ------------------------------------------
__device__ __forceinline__ uint32_t smem_to_u32(const void* p) {
    uint32_t a;
    asm("{ .reg .u64 t; cvta.to.shared.u64 t, %1; cvt.u32.u64 %0, t; }" : "=r"(a) : "l"(p));
    return a;
}
__device__ __forceinline__ void cp_async16(uint32_t saddr, const void* gptr) {
    asm volatile("cp.async.cg.shared.global [%0], [%1], 16;" :: "r"(saddr), "l"(gptr));
}
#define CP_COMMIT() asm volatile("cp.async.commit_group;" ::: "memory")
#define CP_WAIT1()  asm volatile("cp.async.wait_group 1;" ::: "memory")
#define CP_WAIT2()  asm volatile("cp.async.wait_group 2;" ::: "memory")

__device__ __forceinline__ void ldsm_x4(uint32_t* r, uint32_t addr) {
    asm volatile("ldmatrix.sync.aligned.m8n8.x4.shared.b16 {%0,%1,%2,%3}, [%4];"
                 : "=r"(r[0]), "=r"(r[1]), "=r"(r[2]), "=r"(r[3]) : "r"(addr));
}
__device__ __forceinline__ void ldsm_x4_trans(uint32_t* r, uint32_t addr) {
    asm volatile("ldmatrix.sync.aligned.m8n8.x4.trans.shared.b16 {%0,%1,%2,%3}, [%4];"
                 : "=r"(r[0]), "=r"(r[1]), "=r"(r[2]), "=r"(r[3]) : "r"(addr));
}
__device__ __forceinline__ void mma_f16(float* d, const uint32_t* a, const uint32_t* b) {
    asm volatile(
        "mma.sync.aligned.m16n8k16.row.col.f32.f16.f16.f32 "
        "{%0,%1,%2,%3}, {%4,%5,%6,%7}, {%8,%9}, {%0,%1,%2,%3};"
        : "+f"(d[0]), "+f"(d[1]), "+f"(d[2]), "+f"(d[3])
        : "r"(a[0]), "r"(a[1]), "r"(a[2]), "r"(a[3]), "r"(b[0]), "r"(b[1]));
}
__device__ __forceinline__ uint32_t pack2h(__half a, __half b) {
    __half2 t = __halves2half2(a, b);
    return *(uint32_t*)&t;
}
#define SW(o) ((o) ^ (((o) >> 3) & 0x70))

// ---------------- plain fp16 GEMM core macros (4-stage pipeline) --------------
#define BM 128
#define BN 64
#define BK 32
#define NSTAGE 4
#define A_PITCH 80
#define SB_OFF (128 * A_PITCH)
#define STAGE_BYTES (SB_OFF + 64 * A_PITCH)  // 15360
#define GEMM_SMEM (NSTAGE * STAGE_BYTES)     // 61440

#define GEMM_MAINLOOP(A16, B16, K)                                                   \
    const uint32_t sbase = smem_to_u32(smem);                                        \
    const int tid  = threadIdx.x;                                                    \
    const int wid  = tid >> 5;                                                       \
    const int lane = tid & 31;                                                       \
    const int m0 = blockIdx.y * BM;                                                  \
    const int n0 = blockIdx.x * BN;                                                  \
    const int wm = wid >> 1;                                                         \
    const int wn = wid & 1;                                                          \
    const int nchunk = (K) / BK;                                                     \
    const int arow = tid >> 1;                                                       \
    const int acol = (tid & 1) * 2;                                                  \
    const int brow = tid >> 2;                                                       \
    const int bcol = tid & 3;                                                        \
    auto load_stage = [&](int ci, int s) {                                           \
        const uint32_t st = sbase + s * STAGE_BYTES;                                 \
        const int k0 = ci * BK;                                                      \
        {                                                                            \
            const size_t go = (size_t)(m0 + arow) * (K) + k0 + acol * 8;             \
            const uint32_t so = st + arow * A_PITCH + acol * 16;                     \
            cp_async16(so,      (A16) + go);                                         \
            cp_async16(so + 16, (A16) + go + 8);                                     \
        }                                                                            \
        {                                                                            \
            const size_t go = (size_t)(n0 + brow) * (K) + k0 + bcol * 8;             \
            const uint32_t so = st + SB_OFF + brow * A_PITCH + bcol * 16;            \
            cp_async16(so, (B16) + go);                                              \
        }                                                                            \
    };                                                                               \
    float acc[2][4][4];                                                              \
    _Pragma("unroll")                                                                \
    for (int i = 0; i < 2; i++)                                                      \
        _Pragma("unroll")                                                            \
        for (int j = 0; j < 4; j++)                                                  \
            _Pragma("unroll")                                                        \
            for (int v = 0; v < 4; v++) acc[i][j][v] = 0.f;                          \
    load_stage(0, 0); CP_COMMIT();                                                   \
    load_stage(1, 1); CP_COMMIT();                                                   \
    load_stage(2, 2); CP_COMMIT();                                                   \
    const int a_r   = lane & 15;                                                     \
    const int a_cb  = (lane >> 4) * 16;                                              \
    const int b_mat = lane >> 3;                                                     \
    const int b_rin = lane & 7;                                                      \
    const int b_nof = (b_mat >> 1) * 8 + b_rin;                                      \
    const int b_kb  = (b_mat & 1) * 16;                                              \
    for (int i = 0; i < nchunk; i++) {                                               \
        CP_WAIT2();                                                                  \
        __syncthreads();                                                             \
        if (i + 3 < nchunk) load_stage(i + 3, (i + 3) % NSTAGE);                     \
        CP_COMMIT();                                                                 \
        const uint32_t st = sbase + (i % NSTAGE) * STAGE_BYTES;                      \
        _Pragma("unroll")                                                            \
        for (int kk = 0; kk < 2; kk++) {                                             \
            const int kbyte = kk * 32;                                               \
            uint32_t ah[2][4], bh[8];                                                \
            _Pragma("unroll")                                                        \
            for (int mt = 0; mt < 2; mt++) {                                         \
                uint32_t addr = st + (wm * 32 + mt * 16 + a_r) * A_PITCH + kbyte + a_cb; \
                ldsm_x4(ah[mt], addr);                                               \
            }                                                                        \
            _Pragma("unroll")                                                        \
            for (int hh = 0; hh < 2; hh++) {                                         \
                uint32_t addr = st + SB_OFF + (wn * 32 + hh * 16 + b_nof) * A_PITCH + kbyte + b_kb; \
                ldsm_x4(&bh[hh * 4], addr);                                          \
            }                                                                        \
            _Pragma("unroll")                                                        \
            for (int mt = 0; mt < 2; mt++)                                           \
                _Pragma("unroll")                                                    \
                for (int nt = 0; nt < 4; nt++)                                       \
                    mma_f16(acc[mt][nt], ah[mt], &bh[nt * 2]);                       \
        }                                                                            \
        __syncthreads();                                                             \
    }

// ---------------- output-proj GEMM (fp32 epilogue) ----------------------------
__global__ void __launch_bounds__(256, 2)
gemm_out_kernel(const __half* __restrict__ A16,
                const __half* __restrict__ B16,
                float* __restrict__ C, int M, int N, int K)
{
    extern __shared__ __align__(128) char smem[];
    GEMM_MAINLOOP(A16, B16, K)
#pragma unroll
    for (int mt = 0; mt < 2; mt++) {
#pragma unroll
        for (int nt = 0; nt < 4; nt++) {
            const int m = m0 + wm * 32 + mt * 16 + (lane >> 2);
            const int n = n0 + wn * 32 + nt * 8 + (lane & 3) * 2;
            *(float2*)&C[(size_t)m * N + n]       = make_float2(acc[mt][nt][0], acc[mt][nt][1]);
            *(float2*)&C[(size_t)(m + 8) * N + n] = make_float2(acc[mt][nt][2], acc[mt][nt][3]);
        }
    }
}

// ---------------- fused QKV GEMM with RoPE epilogue ---------------------------
__global__ void __launch_bounds__(256, 2)
gemm_qkv_kernel(const __half* __restrict__ A16,
                const __half* __restrict__ B16,
                const float* __restrict__ fcos, const float* __restrict__ fsin)
{
    extern __shared__ __align__(128) char smem[];
    GEMM_MAINLOOP(A16, B16, DIM)

    auto store_pair = [&](int r, int n, float a0, float a1) {
        int t = r & (SEQ - 1);
        if (n < 960) {
            int i = (n & 63) >> 1;
            float c = fcos[t * 32 + i], s = fsin[t * 32 + i];
            *(uint32_t*)(g_q16 + (size_t)r * 960 + n) =
                pack2h(__float2half((a0 * c - a1 * s) * 0.125f),
                       __float2half((a0 * s + a1 * c) * 0.125f));
        } else if (n < 1280) {
            int i = (n & 63) >> 1;
            float c = fcos[t * 32 + i], s = fsin[t * 32 + i];
            *(uint32_t*)(g_k16 + (size_t)r * 320 + (n - 960)) =
                pack2h(__float2half(a0 * c - a1 * s), __float2half(a0 * s + a1 * c));
        } else {
            *(uint32_t*)(g_v16 + (size_t)r * 320 + (n - 1280)) =
                pack2h(__float2half(a0), __float2half(a1));
        }
    };

#pragma unroll
    for (int mt = 0; mt < 2; mt++) {
#pragma unroll
        for (int nt = 0; nt < 4; nt++) {
            const int m = m0 + wm * 32 + mt * 16 + (lane >> 2);
            const int n = n0 + wn * 32 + nt * 8 + (lane & 3) * 2;
            store_pair(m,     n, acc[mt][nt][0], acc[mt][nt][1]);
            store_pair(m + 8, n, acc[mt][nt][2], acc[mt][nt][3]);
        }
    }
}

// ---------------- convert / combined transpose helpers ------------------------
__global__ void convert_f16_kernel(const float* __restrict__ src,
                                   __half* __restrict__ dst, int n) {
    int idx = blockIdx.x * blockDim.x + threadIdx.x;
    if (idx >= n) return;
    dst[idx] = __float2half(src[idx]);
}

__global__ void transpose_all_f16_kernel(const float* __restrict__ wq,
                                         const float* __restrict__ wk,
                                         const float* __restrict__ wv,
                                         const float* __restrict__ wo) {
    __shared__ float tile[32][33];
    const int ng = blockIdx.x * 32;
    const int k0 = blockIdx.y * 32;
    const float* src; __half* dst; int N; int nloc;
    if (ng < 960)       { src = wq; dst = g_wqkv;                      N = 960; nloc = ng; }
    else if (ng < 1280) { src = wk; dst = g_wqkv + (size_t)960 * 960;  N = 320; nloc = ng - 960; }
    else if (ng < 1600) { src = wv; dst = g_wqkv + (size_t)1280 * 960; N = 320; nloc = ng - 1280; }
    else                { src = wo; dst = g_wot;                       N = 960; nloc = ng - 1600; }

    int tx = threadIdx.x, ty = threadIdx.y;
#pragma unroll
    for (int i = 0; i < 4; i++)
        tile[ty + i * 8][tx] = src[(size_t)(k0 + ty + i * 8) * N + nloc + tx];
    __syncthreads();
#pragma unroll
    for (int i = 0; i < 4; i++) {
        int n = nloc + ty + i * 8;
        dst[(size_t)n * 960 + k0 + tx] = __float2half(tile[tx][ty + i * 8]);
    }
}

// ---------------- Flash attention on mma.sync fp16 (causal, GQA) --------------
// Q/K/V/P single fp16, fp32 accum. Q persistent in swizzled smem (no Q regs).
// smem: [0,8192) Q; stage s at 8192+s*16384: K 8192 + V 8192. SW128 swizzle,
// pitch 128 (no padding) -> 40960 B total -> 5 CTAs/SM with <=100 regs.
#define AT_Q 0
#define AT_STAGE0 8192
#define AT_STAGE_SZ 16384
#define AT_V_OFF 8192
#define ATTN_SMEM (8192 + 2 * AT_STAGE_SZ)   // 40960

__global__ void __launch_bounds__(128, 5)
attn_mma_kernel(const __half* __restrict__ Q16,
                const __half* __restrict__ K16, const __half* __restrict__ V16,
                __half* __restrict__ O16)
{
    extern __shared__ __align__(1024) char smem[];
    const uint32_t sbase = smem_to_u32(smem);
    const int tid = threadIdx.x, wid = tid >> 5, lane = tid & 31;
    const int qt = gridDim.x - 1 - blockIdx.x;
    const int h = blockIdx.y, b = blockIdx.z;
    const int kvh = h / GQA;

    // ---- stage Q into persistent swizzled smem
    {
        int r = tid >> 1, half = tid & 1;
        size_t gq = ((size_t)(b * SEQ + qt * 64 + r) * NH + h) * HD + half * 32;
        const uint4* ph = (const uint4*)(Q16 + gq);
#pragma unroll
        for (int c = 0; c < 4; c++) {
            uint32_t off = (uint32_t)(r * 128 + half * 64 + c * 16);
            *(uint4*)(smem + SW(off)) = ph[c];
        }
    }
    __syncthreads();

    auto load_kv = [&](int kt) {
        uint32_t st = sbase + AT_STAGE0 + (kt & 1) * AT_STAGE_SZ;
        int jr = tid >> 1, cs = (tid & 1) * 4;
        size_t g = ((size_t)(b * SEQ + kt * 64 + jr) * NKV + kvh) * HD + cs * 8;
#pragma unroll
        for (int c = 0; c < 4; c++) {
            uint32_t off = SW((uint32_t)(jr * 128 + (cs + c) * 16));
            cp_async16(st + off,            K16 + g + c * 8);
            cp_async16(st + AT_V_OFF + off, V16 + g + c * 8);
        }
    };

    float O[8][4];
#pragma unroll
    for (int i = 0; i < 8; i++)
#pragma unroll
        for (int j = 0; j < 4; j++) O[i][j] = 0.f;
    float m0 = -CUDART_INF_F, m1 = -CUDART_INF_F;
    float l0 = 0.f, l1 = 0.f;

    load_kv(0); CP_COMMIT();
    if (qt >= 1) load_kv(1);
    CP_COMMIT();

    const int a_r   = lane & 15;
    const int a_cb  = (lane >> 4) * 16;
    const int b_rin = lane & 7;
    const int b_mat = lane >> 3;
    const int b_nof = (b_mat >> 1) * 8 + b_rin;
    const int b_kb  = (b_mat & 1) * 16;
    const int v_r   = lane & 15;
    const int v_cb  = (lane >> 4) * 16;
    const int r0loc = wid * 16 + (lane >> 2);

    for (int kt = 0; kt <= qt; kt++) {
        CP_WAIT1();
        __syncthreads();
        const uint32_t st = sbase + AT_STAGE0 + (kt & 1) * AT_STAGE_SZ;

        // ---- S = Q K^T (1-pass fp16; Q fragment re-loaded from smem)
        float S[8][4];
#pragma unroll
        for (int i = 0; i < 8; i++)
#pragma unroll
            for (int j = 0; j < 4; j++) S[i][j] = 0.f;

#pragma unroll
        for (int kk = 0; kk < 4; kk++) {
            uint32_t qf[4];
            ldsm_x4(qf, sbase + SW((uint32_t)((wid * 16 + a_r) * 128 + kk * 32 + a_cb)));
            uint32_t kb[16];
#pragma unroll
            for (int g2 = 0; g2 < 4; g2++) {
                uint32_t addr = st + SW((uint32_t)((g2 * 16 + b_nof) * 128 + kk * 32 + b_kb));
                ldsm_x4(&kb[g2 * 4], addr);
            }
#pragma unroll
            for (int nt = 0; nt < 8; nt++)
                mma_f16(S[nt], qf, &kb[nt * 2]);
        }

        // ---- causal mask (diag tile only)
        if (kt == qt) {
#pragma unroll
            for (int nt = 0; nt < 8; nt++) {
                int col = nt * 8 + (lane & 3) * 2;
                if (col     > r0loc)     S[nt][0] = -CUDART_INF_F;
                if (col + 1 > r0loc)     S[nt][1] = -CUDART_INF_F;
                if (col     > r0loc + 8) S[nt][2] = -CUDART_INF_F;
                if (col + 1 > r0loc + 8) S[nt][3] = -CUDART_INF_F;
            }
        }

        // ---- online softmax
        float t0 = -CUDART_INF_F, t1 = -CUDART_INF_F;
#pragma unroll
        for (int nt = 0; nt < 8; nt++) {
            t0 = fmaxf(t0, fmaxf(S[nt][0], S[nt][1]));
            t1 = fmaxf(t1, fmaxf(S[nt][2], S[nt][3]));
        }
        t0 = fmaxf(t0, __shfl_xor_sync(0xffffffffu, t0, 1));
        t0 = fmaxf(t0, __shfl_xor_sync(0xffffffffu, t0, 2));
        t1 = fmaxf(t1, __shfl_xor_sync(0xffffffffu, t1, 1));
        t1 = fmaxf(t1, __shfl_xor_sync(0xffffffffu, t1, 2));
        float mn0 = fmaxf(m0, t0), mn1 = fmaxf(m1, t1);
        float c0 = __expf(m0 - mn0), c1 = __expf(m1 - mn1);
        m0 = mn0; m1 = mn1;

        // ---- P = exp(S - m), single fp16 (l accumulated in fp32)
        uint32_t pk[4][4];
        float la0 = 0.f, la1 = 0.f;
#pragma unroll
        for (int t = 0; t < 4; t++) {
            float p[8];
            p[0] = __expf(S[2*t][0] - mn0);   p[1] = __expf(S[2*t][1] - mn0);
            p[2] = __expf(S[2*t][2] - mn1);   p[3] = __expf(S[2*t][3] - mn1);
            p[4] = __expf(S[2*t+1][0] - mn0); p[5] = __expf(S[2*t+1][1] - mn0);
            p[6] = __expf(S[2*t+1][2] - mn1); p[7] = __expf(S[2*t+1][3] - mn1);
            la0 += p[0] + p[1] + p[4] + p[5];
            la1 += p[2] + p[3] + p[6] + p[7];
            pk[t][0] = pack2h(__float2half(p[0]), __float2half(p[1]));
            pk[t][1] = pack2h(__float2half(p[2]), __float2half(p[3]));
            pk[t][2] = pack2h(__float2half(p[4]), __float2half(p[5]));
            pk[t][3] = pack2h(__float2half(p[6]), __float2half(p[7]));
        }
        l0 = l0 * c0 + la0;
        l1 = l1 * c1 + la1;

#pragma unroll
        for (int dt = 0; dt < 8; dt++) {
            O[dt][0] *= c0; O[dt][1] *= c0;
            O[dt][2] *= c1; O[dt][3] *= c1;
        }

        // ---- O += P V (1-pass fp16)
#pragma unroll
        for (int t = 0; t < 4; t++) {
            uint32_t vb[16];
#pragma unroll
            for (int db = 0; db < 4; db++) {
                uint32_t addr = st + AT_V_OFF +
                    SW((uint32_t)((t * 16 + v_r) * 128 + db * 32 + v_cb));
                ldsm_x4_trans(&vb[db * 4], addr);
            }
#pragma unroll
            for (int dt = 0; dt < 8; dt++)
                mma_f16(O[dt], pk[t], &vb[dt * 2]);
        }

        __syncthreads();
        if (kt + 2 <= qt) load_kv(kt + 2);
        CP_COMMIT();
    }

    // ---- finalize: normalize, store fp16
    l0 += __shfl_xor_sync(0xffffffffu, l0, 1);
    l0 += __shfl_xor_sync(0xffffffffu, l0, 2);
    l1 += __shfl_xor_sync(0xffffffffu, l1, 1);
    l1 += __shfl_xor_sync(0xffffffffu, l1, 2);
    float inv0 = 1.f / l0, inv1 = 1.f / l1;

    const int row0 = qt * 64 + r0loc;
#pragma unroll
    for (int dt = 0; dt < 8; dt++) {
        int d = dt * 8 + (lane & 3) * 2;
        size_t o0 = ((size_t)(b * SEQ + row0) * NH + h) * HD + d;
        size_t o1 = o0 + (size_t)8 * NH * HD;
        *(uint32_t*)(O16 + o0) = pack2h(__float2half(O[dt][0] * inv0),
                                        __float2half(O[dt][1] * inv0));
        *(uint32_t*)(O16 + o1) = pack2h(__float2half(O[dt][2] * inv1),
                                        __float2half(O[dt][3] * inv1));
    }
}

// ---------------- launcher ----------------------------------------------------
extern "C" void kernel_launch(void* const* d_in, const int* in_sizes, int n_in,
                              void* d_out, int out_size) {
    const float* x    = (const float*)d_in[0];
    const float* fcos = (const float*)d_in[1];
    const float* fsin = (const float*)d_in[2];
    const float* wq   = (const float*)d_in[3];
    const float* wk   = (const float*)d_in[4];
    const float* wv   = (const float*)d_in[5];
    const float* wo   = (const float*)d_in[6];
    float* out = (float*)d_out;

    __half *x16, *o16, *q16, *k16, *v16, *wqkv, *wot;
    cudaGetSymbolAddress((void**)&x16, g_x16);
    cudaGetSymbolAddress((void**)&o16, g_o16);
    cudaGetSymbolAddress((void**)&q16, g_q16);
    cudaGetSymbolAddress((void**)&k16, g_k16);
    cudaGetSymbolAddress((void**)&v16, g_v16);
    cudaGetSymbolAddress((void**)&wqkv, g_wqkv);
    cudaGetSymbolAddress((void**)&wot, g_wot);

    cudaFuncSetAttribute(gemm_out_kernel,
                         cudaFuncAttributeMaxDynamicSharedMemorySize, GEMM_SMEM);
    cudaFuncSetAttribute(gemm_qkv_kernel,
                         cudaFuncAttributeMaxDynamicSharedMemorySize, GEMM_SMEM);
    cudaFuncSetAttribute(attn_mma_kernel,
                         cudaFuncAttributeMaxDynamicSharedMemorySize, ATTN_SMEM);

    // input -> fp16; all weight transposes in one launch
    {
        int n = MTOK * DIM;
        convert_f16_kernel<<<(n + 255) / 256, 256>>>(x, x16, n);
    }
    transpose_all_f16_kernel<<<dim3(2560 / 32, 960 / 32), dim3(32, 8)>>>(wq, wk, wv, wo);

    // fused QKV projection + RoPE epilogue (fp16 1-pass GEMM)
    gemm_qkv_kernel<<<dim3(QKV_N / BN, MTOK / BM), 256, GEMM_SMEM>>>(
        x16, wqkv, fcos, fsin);

    // flash attention (fp16 tensor cores)
    attn_mma_kernel<<<dim3(SEQ / 64, NH, BATCH), 128, ATTN_SMEM>>>(
        q16, k16, v16, o16);

    // output projection (fp16 1-pass GEMM)
    gemm_out_kernel<<<dim3(960 / BN, MTOK / BM), 256, GEMM_SMEM>>>(
        o16, wot, out, MTOK, 960, 960);
}